// round 1
// baseline (speedup 1.0000x reference)
#include <cuda_runtime.h>
#include <math.h>

#define NN    20000     // N_U == N_I
#define DIM   256
#define NNZ_  600000
#define NE_   300000
#define B_    8192

// ---------------- persistent device scratch (no allocations allowed) -------
__device__ float d_hg[NN*DIM], d_hd[NN*DIM];
__device__ float d_numg[NN*DIM], d_numd[NN*DIM];
__device__ float d_Eg0b[NN*DIM], d_Ed0b[NN*DIM];
__device__ float d_Eg[NN*DIM], d_Ed[NN*DIM];
__device__ float d_alg[NN], d_arg_[NN], d_ald[NN], d_ard[NN];
__device__ float d_mg[NN], d_md[NN], d_deng[NN], d_dend[NN];
__device__ float d_ebg[NE_], d_ebd[NE_];
__device__ float d_inp[B_*2*DIM], d_inn[B_*2*DIM];
__device__ float d_h1p[B_*DIM], d_h1n[B_*DIM], d_h2p[B_*DIM], d_h2n[B_*DIM];
__device__ float d_spv[B_], d_snv[B_];
__device__ double d_lr_acc, d_reg_acc;

// ---------------- helpers --------------------------------------------------
__device__ __forceinline__ void atomicMaxF(float* addr, float val){
    int* ia = (int*)addr;
    int old = *ia;
    while (__int_as_float(old) < val){
        int assumed = old;
        old = atomicCAS(ia, assumed, __float_as_int(val));
        if (old == assumed) break;
    }
}

__device__ __forceinline__ double softplusd(double x){
    return fmax(x, 0.0) + log1p(exp(-fabs(x)));
}

// ---------------- init -----------------------------------------------------
__global__ void init_k(float* mg, float* md, int n, double* lr, double* reg){
    int i = blockIdx.x*blockDim.x + threadIdx.x;
    if (i < n){ mg[i] = -1e30f; md[i] = -1e30f; }
    if (i == 0){ *lr = 0.0; *reg = 0.0; }
}

// ---------------- tiled fp32 GEMM: C[M,N] = A[M,K] @ B[K,N] (+bias,relu) ---
// BM=BN=64, BK=16, 256 threads, 4x4 per-thread microtile.
__global__ void sgemm_k(int M, int N, int K,
                        const float* __restrict__ A, const float* __restrict__ B,
                        float* __restrict__ C, const float* __restrict__ bias, int relu){
    __shared__ float As[16][65];
    __shared__ float Bs[16][64];
    int tid  = threadIdx.x;
    int col0 = blockIdx.x * 64;
    int row0 = blockIdx.y * 64;
    int tx = tid & 15, ty = tid >> 4;
    float acc[4][4] = {};
    for (int k0 = 0; k0 < K; k0 += 16){
        #pragma unroll
        for (int i = 0; i < 4; i++){
            int e = tid + i*256;
            int r = e >> 4, c = e & 15;
            int gr = row0 + r;
            As[c][r] = (gr < M) ? A[(size_t)gr*K + k0 + c] : 0.f;
            int r2 = e >> 6, c2 = e & 63;
            Bs[r2][c2] = B[(size_t)(k0 + r2)*N + col0 + c2];
        }
        __syncthreads();
        #pragma unroll
        for (int k = 0; k < 16; k++){
            float ra[4], rb[4];
            #pragma unroll
            for (int m = 0; m < 4; m++) ra[m] = As[k][ty*4 + m];
            #pragma unroll
            for (int n = 0; n < 4; n++) rb[n] = Bs[k][tx*4 + n];
            #pragma unroll
            for (int m = 0; m < 4; m++)
                #pragma unroll
                for (int n = 0; n < 4; n++) acc[m][n] += ra[m]*rb[n];
        }
        __syncthreads();
    }
    #pragma unroll
    for (int m = 0; m < 4; m++){
        int r = row0 + ty*4 + m;
        if (r >= M) continue;
        #pragma unroll
        for (int n = 0; n < 4; n++){
            int c = col0 + tx*4 + n;
            float v = acc[m][n];
            if (bias) v += bias[c];
            if (relu) v = fmaxf(v, 0.f);
            C[(size_t)r*N + c] = v;
        }
    }
}

// ---------------- per-node dot with attention vector: al=h@a[:D], ar=h@a[D:]
__global__ void rowdot_k(const float* __restrict__ h, const float* __restrict__ a,
                         float* __restrict__ al, float* __restrict__ ar, int n){
    int w = (blockIdx.x*blockDim.x + threadIdx.x) >> 5;
    int lane = threadIdx.x & 31;
    if (w >= n) return;
    const float* hr = h + (size_t)w*DIM;
    float a1 = 0.f, a2 = 0.f;
    for (int k = lane; k < DIM; k += 32){
        float hv = hr[k];
        a1 += hv * a[k];
        a2 += hv * a[DIM + k];
    }
    #pragma unroll
    for (int o = 16; o; o >>= 1){
        a1 += __shfl_xor_sync(0xffffffffu, a1, o);
        a2 += __shfl_xor_sync(0xffffffffu, a2, o);
    }
    if (lane == 0){ al[w] = a1; ar[w] = a2; }
}

// ---------------- edge pass 1: e = leaky_relu(al[src]+ar[tgt]); segment max
__global__ void edge_max_k(const int* __restrict__ src, const int* __restrict__ tgt,
                           const float* __restrict__ al, const float* __restrict__ ar,
                           float* __restrict__ ebuf, float* __restrict__ m, int E){
    int i = blockIdx.x*blockDim.x + threadIdx.x;
    if (i >= E) return;
    float x = al[src[i]] + ar[tgt[i]];
    float e = x > 0.f ? x : 0.2f*x;
    ebuf[i] = e;
    atomicMaxF(&m[tgt[i]], e);
}

// ---------------- edge pass 2: ex=exp(e-m[t]); denom += ex; num += ex*h[src]
__global__ void edge_acc_k(const int* __restrict__ src, const int* __restrict__ tgt,
                           const float* __restrict__ ebuf, const float* __restrict__ m,
                           const float* __restrict__ h,
                           float* __restrict__ den, float* __restrict__ num, int E){
    int gi = blockIdx.x*blockDim.x + threadIdx.x;
    if (gi >= E*64) return;
    int e = gi >> 6;
    int q = (gi & 63) << 2;
    int t = tgt[e];
    float ex = expf(ebuf[e] - m[t]);
    if (q == 0) atomicAdd(&den[t], ex);
    int s = src[e];
    float4 hv = *(const float4*)(h + (size_t)s*DIM + q);
    float* np = num + (size_t)t*DIM + q;
    atomicAdd(np    , ex*hv.x);
    atomicAdd(np + 1, ex*hv.y);
    atomicAdd(np + 2, ex*hv.z);
    atomicAdd(np + 3, ex*hv.w);
}

// ---------------- out = 0.1*num/(den+1e-9) + base --------------------------
__global__ void combine_emb_k(const float* __restrict__ num, const float* __restrict__ den,
                              const float* __restrict__ base, float* __restrict__ out, int n){
    int gi = blockIdx.x*blockDim.x + threadIdx.x;
    if (gi >= n*64) return;
    int node = gi >> 6;
    int j = (gi & 63) << 2;
    float dinv = 0.1f / (den[node] + 1e-9f);
    float4 nu = *(const float4*)(num  + (size_t)node*DIM + j);
    float4 ba = *(const float4*)(base + (size_t)node*DIM + j);
    float4 o;
    o.x = nu.x*dinv + ba.x;
    o.y = nu.y*dinv + ba.y;
    o.z = nu.z*dinv + ba.z;
    o.w = nu.w*dinv + ba.w;
    *(float4*)(out + (size_t)node*DIM + j) = o;
}

// ---------------- sparse dropout + SpMM: dst[rows] += v*mask*scale * src[cols]
__global__ void spmm_k(const int* __restrict__ rows, const int* __restrict__ cols,
                       const float* __restrict__ vals, const unsigned* __restrict__ mask,
                       const float* __restrict__ src, float* __restrict__ dst, int E){
    int gi = blockIdx.x*blockDim.x + threadIdx.x;
    if (gi >= E*64) return;
    int n = gi >> 6;
    if (mask[n] == 0u) return;            // bool as 4-byte (i32 or f32): nonzero == keep
    int q = (gi & 63) << 2;
    float v = vals[n] * (1.0f/0.9f);
    int c = cols[n], r = rows[n];
    float4 s = *(const float4*)(src + (size_t)c*DIM + q);
    float* dp = dst + (size_t)r*DIM + q;
    atomicAdd(dp    , v*s.x);
    atomicAdd(dp + 1, v*s.y);
    atomicAdd(dp + 2, v*s.z);
    atomicAdd(dp + 3, v*s.w);
}

// ---------------- gather [u, item] into [B, 512] ---------------------------
__global__ void gather_k(const float* __restrict__ Eg, const float* __restrict__ Ed,
                         const int* __restrict__ uids, const int* __restrict__ iidx,
                         float* __restrict__ out, int B){
    int gi = blockIdx.x*blockDim.x + threadIdx.x;
    if (gi >= B*128) return;
    int b = gi >> 7;
    int j = (gi & 127) << 2;
    float4 v;
    if (j < DIM) v = *(const float4*)(Eg + (size_t)uids[b]*DIM + j);
    else         v = *(const float4*)(Ed + (size_t)iidx[b]*DIM + (j - DIM));
    *(float4*)(out + (size_t)b*(2*DIM) + j) = v;
}

// ---------------- final linear layer: s = h2 @ W3 + b3 ---------------------
__global__ void score_k(const float* __restrict__ h2p, const float* __restrict__ h2n,
                        const float* __restrict__ W3, const float* __restrict__ b3,
                        float* __restrict__ sp, float* __restrict__ sn, int B){
    int w = (blockIdx.x*blockDim.x + threadIdx.x) >> 5;
    int lane = threadIdx.x & 31;
    if (w >= 2*B) return;
    const float* h2 = (w < B) ? h2p : h2n;
    int b = (w < B) ? w : w - B;
    float acc = 0.f;
    const float* hr = h2 + (size_t)b*DIM;
    for (int k = lane; k < DIM; k += 32) acc += hr[k] * W3[k];
    #pragma unroll
    for (int o = 16; o; o >>= 1) acc += __shfl_xor_sync(0xffffffffu, acc, o);
    if (lane == 0){
        float v = acc + b3[0];
        if (w < B) sp[b] = v; else sn[b] = v;
    }
}

// ---------------- loss_r reduction -----------------------------------------
__global__ void loss_k(const float* __restrict__ sp, const float* __restrict__ sn,
                       int B, double* acc){
    __shared__ double sh[256];
    double local = 0.0;
    for (int i = blockIdx.x*blockDim.x + threadIdx.x; i < B; i += gridDim.x*blockDim.x){
        double ps = sp[i], ns = sn[i];
        local += softplusd(-ps) + softplusd(ns) + softplusd(ns - ps);
    }
    sh[threadIdx.x] = local;
    __syncthreads();
    for (int s = 128; s; s >>= 1){
        if (threadIdx.x < s) sh[threadIdx.x] += sh[threadIdx.x + s];
        __syncthreads();
    }
    if (threadIdx.x == 0) atomicAdd(acc, sh[0]);
}

// ---------------- sum of squares (regularizer) ------------------------------
__global__ void sumsq_k(const float* __restrict__ p, int n, double* acc){
    __shared__ double sh[256];
    double local = 0.0;
    for (int i = blockIdx.x*blockDim.x + threadIdx.x; i < n; i += gridDim.x*blockDim.x){
        double v = p[i];
        local += v*v;
    }
    sh[threadIdx.x] = local;
    __syncthreads();
    for (int s = 128; s; s >>= 1){
        if (threadIdx.x < s) sh[threadIdx.x] += sh[threadIdx.x + s];
        __syncthreads();
    }
    if (threadIdx.x == 0) atomicAdd(acc, sh[0]);
}

// ---------------- final combine --------------------------------------------
__global__ void final_k(const double* lr, const double* reg, float* out, int B){
    double l_r = (*lr) / (double)B;
    out[0] = (float)(1e-7 * (*reg) + l_r);
    out[1] = (float)l_r;
    out[2] = 0.f;
}

// ---------------- launch ----------------------------------------------------
extern "C" void kernel_launch(void* const* d_in, const int* in_sizes, int n_in,
                              void* d_out, int out_size){
    const float* Eg0  = (const float*)d_in[0];
    const float* Ed0  = (const float*)d_in[1];
    const float* attW = (const float*)d_in[2];
    const float* atta = (const float*)d_in[3];
    const float* W1   = (const float*)d_in[6];
    const float* b1   = (const float*)d_in[7];
    const float* W2   = (const float*)d_in[8];
    const float* b2   = (const float*)d_in[9];
    const float* W3   = (const float*)d_in[10];
    const float* b3   = (const float*)d_in[11];
    const float* adj_vals = (const float*)d_in[16];
    const int* uids = (const int*)d_in[17];
    const int* pos  = (const int*)d_in[19];
    const int* neg  = (const int*)d_in[20];
    const int* ge   = (const int*)d_in[21];
    const int* de   = (const int*)d_in[22];
    const int* arows = (const int*)d_in[23];
    const int* acols = (const int*)d_in[24];
    const unsigned* drop1 = (const unsigned*)d_in[25];
    const unsigned* drop2 = (const unsigned*)d_in[26];
    float* out = (float*)d_out;

    float *hg,*hd,*numg,*numd,*Eg0b,*Ed0b,*Eg,*Ed;
    float *alg,*arg,*ald,*ard,*mg,*md,*deng,*dend,*ebg,*ebd;
    float *inp,*inn,*h1p,*h1n,*h2p,*h2n,*spv,*snv;
    double *lr,*reg;
    cudaGetSymbolAddress((void**)&hg,   d_hg);
    cudaGetSymbolAddress((void**)&hd,   d_hd);
    cudaGetSymbolAddress((void**)&numg, d_numg);
    cudaGetSymbolAddress((void**)&numd, d_numd);
    cudaGetSymbolAddress((void**)&Eg0b, d_Eg0b);
    cudaGetSymbolAddress((void**)&Ed0b, d_Ed0b);
    cudaGetSymbolAddress((void**)&Eg,   d_Eg);
    cudaGetSymbolAddress((void**)&Ed,   d_Ed);
    cudaGetSymbolAddress((void**)&alg,  d_alg);
    cudaGetSymbolAddress((void**)&arg,  d_arg_);
    cudaGetSymbolAddress((void**)&ald,  d_ald);
    cudaGetSymbolAddress((void**)&ard,  d_ard);
    cudaGetSymbolAddress((void**)&mg,   d_mg);
    cudaGetSymbolAddress((void**)&md,   d_md);
    cudaGetSymbolAddress((void**)&deng, d_deng);
    cudaGetSymbolAddress((void**)&dend, d_dend);
    cudaGetSymbolAddress((void**)&ebg,  d_ebg);
    cudaGetSymbolAddress((void**)&ebd,  d_ebd);
    cudaGetSymbolAddress((void**)&inp,  d_inp);
    cudaGetSymbolAddress((void**)&inn,  d_inn);
    cudaGetSymbolAddress((void**)&h1p,  d_h1p);
    cudaGetSymbolAddress((void**)&h1n,  d_h1n);
    cudaGetSymbolAddress((void**)&h2p,  d_h2p);
    cudaGetSymbolAddress((void**)&h2n,  d_h2n);
    cudaGetSymbolAddress((void**)&spv,  d_spv);
    cudaGetSymbolAddress((void**)&snv,  d_snv);
    cudaGetSymbolAddress((void**)&lr,   d_lr_acc);
    cudaGetSymbolAddress((void**)&reg,  d_reg_acc);

    // zero accumulators
    cudaMemsetAsync(numg, 0, sizeof(float)*NN*DIM);
    cudaMemsetAsync(numd, 0, sizeof(float)*NN*DIM);
    cudaMemsetAsync(deng, 0, sizeof(float)*NN);
    cudaMemsetAsync(dend, 0, sizeof(float)*NN);
    cudaMemsetAsync(Eg,   0, sizeof(float)*NN*DIM);
    cudaMemsetAsync(Ed,   0, sizeof(float)*NN*DIM);
    init_k<<<(NN+255)/256, 256>>>(mg, md, NN, lr, reg);

    // h = X @ att_W for both node sets
    sgemm_k<<<dim3(DIM/64, (NN+63)/64), 256>>>(NN, DIM, DIM, Eg0, attW, hg, nullptr, 0);
    sgemm_k<<<dim3(DIM/64, (NN+63)/64), 256>>>(NN, DIM, DIM, Ed0, attW, hd, nullptr, 0);

    // attention logits components
    rowdot_k<<<(NN*32)/256, 256>>>(hg, atta, alg, arg, NN);
    rowdot_k<<<(NN*32)/256, 256>>>(hd, atta, ald, ard, NN);

    // segment max over edges
    edge_max_k<<<(NE_+255)/256, 256>>>(ge, ge+NE_, alg, arg, ebg, mg, NE_);
    edge_max_k<<<(NE_+255)/256, 256>>>(de, de+NE_, ald, ard, ebd, md, NE_);

    // softmax numer/denom accumulation
    edge_acc_k<<<(NE_*64)/256, 256>>>(ge, ge+NE_, ebg, mg, hg, deng, numg, NE_);
    edge_acc_k<<<(NE_*64)/256, 256>>>(de, de+NE_, ebd, md, hd, dend, numd, NE_);

    // E_x0 = 0.1*attn + E_x_0
    combine_emb_k<<<(NN*64)/256, 256>>>(numg, deng, Eg0, Eg0b, NN);
    combine_emb_k<<<(NN*64)/256, 256>>>(numd, dend, Ed0, Ed0b, NN);

    // sparse dropout + SpMM (two independent dropout draws)
    spmm_k<<<(NNZ_*64)/256, 256>>>(arows, acols, adj_vals, drop1, Ed0b, Eg, NNZ_);
    spmm_k<<<(NNZ_*64)/256, 256>>>(acols, arows, adj_vals, drop2, Eg0b, Ed, NNZ_);

    // gather MLP inputs
    gather_k<<<(B_*128)/256, 256>>>(Eg, Ed, uids, pos, inp, B_);
    gather_k<<<(B_*128)/256, 256>>>(Eg, Ed, uids, neg, inn, B_);

    // MLP
    sgemm_k<<<dim3(DIM/64, B_/64), 256>>>(B_, DIM, 2*DIM, inp, W1, h1p, b1, 1);
    sgemm_k<<<dim3(DIM/64, B_/64), 256>>>(B_, DIM, 2*DIM, inn, W1, h1n, b1, 1);
    sgemm_k<<<dim3(DIM/64, B_/64), 256>>>(B_, DIM, DIM,   h1p, W2, h2p, b2, 1);
    sgemm_k<<<dim3(DIM/64, B_/64), 256>>>(B_, DIM, DIM,   h1n, W2, h2n, b2, 1);
    score_k<<<(2*B_*32)/256, 256>>>(h2p, h2n, W3, b3, spv, snv, B_);

    // losses
    loss_k<<<64, 256>>>(spv, snv, B_, lr);
    for (int i = 0; i < 16; i++){
        int n = in_sizes[i];
        int blocks = (n + 255) / 256;
        if (blocks > 512) blocks = 512;
        sumsq_k<<<blocks, 256>>>((const float*)d_in[i], n, reg);
    }
    final_k<<<1, 1>>>(lr, reg, out, B_);
}

// round 2
// speedup vs baseline: 1.6149x; 1.6149x over previous
#include <cuda_runtime.h>
#include <math.h>

#define NN    20000     // N_U == N_I
#define DIM   256
#define NNZ_  600000
#define NE_   300000
#define B_    8192

// ---------------- persistent device scratch (no allocations allowed) -------
__device__ float d_hg[NN*DIM], d_hd[NN*DIM];
__device__ float d_numg[NN*DIM], d_numd[NN*DIM];
__device__ float d_Eg0b[NN*DIM], d_Ed0b[NN*DIM];
__device__ float d_Eg[NN*DIM], d_Ed[NN*DIM];
__device__ float d_alg[NN], d_arg_[NN], d_ald[NN], d_ard[NN];
__device__ float d_mg[NN], d_md[NN], d_deng[NN], d_dend[NN];
__device__ float d_ebg[NE_], d_ebd[NE_];
__device__ float d_w1[NNZ_], d_w2[NNZ_];
__device__ float d_cat[2*B_*2*DIM];           // [2B, 512] pos rows then neg rows
__device__ float d_h1[2*B_*DIM], d_h2[2*B_*DIM];
__device__ float d_s[2*B_];
__device__ double d_lr_acc, d_reg_acc;

// ---------------- helpers --------------------------------------------------
__device__ __forceinline__ void atomicMaxF(float* addr, float val){
    int* ia = (int*)addr;
    int old = *ia;
    while (__int_as_float(old) < val){
        int assumed = old;
        old = atomicCAS(ia, assumed, __float_as_int(val));
        if (old == assumed) break;
    }
}

__device__ __forceinline__ void redAdd4(float* p, float a, float b, float c, float d){
    asm volatile("red.global.add.v4.f32 [%0], {%1,%2,%3,%4};"
                 :: "l"(p), "f"(a), "f"(b), "f"(c), "f"(d) : "memory");
}

__device__ __forceinline__ double softplusd(double x){
    return fmax(x, 0.0) + log1p(exp(-fabs(x)));
}

// ---------------- init -----------------------------------------------------
__global__ void init_k(float* mg, float* md, int n, double* lr, double* reg){
    int i = blockIdx.x*blockDim.x + threadIdx.x;
    if (i < n){ mg[i] = -1e30f; md[i] = -1e30f; }
    if (i == 0){ *lr = 0.0; *reg = 0.0; }
}

// ---------------- 128x128x16 fp32 GEMM, 8x8 microtile, optional 2-batch ----
// C[M,N] = A[M,K] @ B[K,N] (+bias, relu).  Requires N % 128 == 0, K % 16 == 0.
__global__ void sgemm128_k(int M, int N, int K,
                           const float* __restrict__ A0, const float* __restrict__ A1,
                           const float* __restrict__ Bm,
                           float* __restrict__ C0, float* __restrict__ C1,
                           const float* __restrict__ bias, int relu){
    const float* A = blockIdx.z ? A1 : A0;
    float*       C = blockIdx.z ? C1 : C0;
    __shared__ float As[16][132];   // transposed A tile, 132*4=528 bytes/row (16B-aligned)
    __shared__ float Bs[16][128];
    int tid  = threadIdx.x;
    int row0 = blockIdx.y * 128;
    int col0 = blockIdx.x * 128;
    int tx = tid & 15, ty = tid >> 4;
    float acc[8][8] = {};
    for (int k0 = 0; k0 < K; k0 += 16){
        #pragma unroll
        for (int i = 0; i < 2; i++){
            int idx = tid + i*256;
            // A: 128 rows x 16 cols, float4 per thread, store transposed
            int r = idx >> 2, c = (idx & 3) << 2;
            int gr = row0 + r;
            float4 av = (gr < M) ? *(const float4*)(A + (size_t)gr*K + k0 + c)
                                 : make_float4(0.f,0.f,0.f,0.f);
            As[c  ][r] = av.x; As[c+1][r] = av.y; As[c+2][r] = av.z; As[c+3][r] = av.w;
            // B: 16 rows x 128 cols, float4 per thread
            int br = idx >> 5, bc = (idx & 31) << 2;
            *(float4*)&Bs[br][bc] = *(const float4*)(Bm + (size_t)(k0 + br)*N + col0 + bc);
        }
        __syncthreads();
        #pragma unroll
        for (int k = 0; k < 16; k++){
            float4 a0 = *(float4*)&As[k][ty*8];
            float4 a1 = *(float4*)&As[k][ty*8 + 4];
            float4 b0 = *(float4*)&Bs[k][tx*8];
            float4 b1 = *(float4*)&Bs[k][tx*8 + 4];
            float ra[8] = {a0.x,a0.y,a0.z,a0.w,a1.x,a1.y,a1.z,a1.w};
            float rb[8] = {b0.x,b0.y,b0.z,b0.w,b1.x,b1.y,b1.z,b1.w};
            #pragma unroll
            for (int m = 0; m < 8; m++)
                #pragma unroll
                for (int n = 0; n < 8; n++) acc[m][n] += ra[m]*rb[n];
        }
        __syncthreads();
    }
    #pragma unroll
    for (int m = 0; m < 8; m++){
        int r = row0 + ty*8 + m;
        if (r >= M) continue;
        #pragma unroll
        for (int n = 0; n < 8; n += 4){
            int c = col0 + tx*8 + n;
            float4 v = make_float4(acc[m][n], acc[m][n+1], acc[m][n+2], acc[m][n+3]);
            if (bias){ v.x += bias[c]; v.y += bias[c+1]; v.z += bias[c+2]; v.w += bias[c+3]; }
            if (relu){
                v.x = fmaxf(v.x, 0.f); v.y = fmaxf(v.y, 0.f);
                v.z = fmaxf(v.z, 0.f); v.w = fmaxf(v.w, 0.f);
            }
            *(float4*)(C + (size_t)r*N + c) = v;
        }
    }
}

// ---------------- per-node dot with attention vector: al=h@a[:D], ar=h@a[D:]
__global__ void rowdot_k(const float* __restrict__ h, const float* __restrict__ a,
                         float* __restrict__ al, float* __restrict__ ar, int n){
    int w = (blockIdx.x*blockDim.x + threadIdx.x) >> 5;
    int lane = threadIdx.x & 31;
    if (w >= n) return;
    const float* hr = h + (size_t)w*DIM;
    float a1 = 0.f, a2 = 0.f;
    for (int k = lane*4; k < DIM; k += 128){
        float4 hv = *(const float4*)(hr + k);
        float4 av = *(const float4*)(a + k);
        float4 bv = *(const float4*)(a + DIM + k);
        a1 += hv.x*av.x + hv.y*av.y + hv.z*av.z + hv.w*av.w;
        a2 += hv.x*bv.x + hv.y*bv.y + hv.z*bv.z + hv.w*bv.w;
    }
    #pragma unroll
    for (int o = 16; o; o >>= 1){
        a1 += __shfl_xor_sync(0xffffffffu, a1, o);
        a2 += __shfl_xor_sync(0xffffffffu, a2, o);
    }
    if (lane == 0){ al[w] = a1; ar[w] = a2; }
}

// ---------------- edge pass 1: e = leaky_relu(al[src]+ar[tgt]); segment max
__global__ void edge_max_k(const int* __restrict__ src, const int* __restrict__ tgt,
                           const float* __restrict__ al, const float* __restrict__ ar,
                           float* __restrict__ ebuf, float* __restrict__ m, int E){
    int i = blockIdx.x*blockDim.x + threadIdx.x;
    if (i >= E) return;
    float x = al[src[i]] + ar[tgt[i]];
    float e = x > 0.f ? x : 0.2f*x;
    ebuf[i] = e;
    atomicMaxF(&m[tgt[i]], e);
}

// ---------------- edge pass 2: ebuf <- exp(e - m[t]); den[t] += ex ----------
__global__ void edge_exp_k(const int* __restrict__ tgt, float* __restrict__ ebuf,
                           const float* __restrict__ m, float* __restrict__ den, int E){
    int i = blockIdx.x*blockDim.x + threadIdx.x;
    if (i >= E) return;
    int t = tgt[i];
    float ex = __expf(ebuf[i] - m[t]);
    ebuf[i] = ex;
    atomicAdd(&den[t], ex);
}

// ---------------- edge pass 3: num[tgt] += ex * h[src] (vector red) --------
__global__ void edge_acc_k(const int* __restrict__ src, const int* __restrict__ tgt,
                           const float* __restrict__ ebuf,
                           const float* __restrict__ h, float* __restrict__ num, int E){
    int gi = blockIdx.x*blockDim.x + threadIdx.x;
    if (gi >= E*64) return;
    int e = gi >> 6;
    int q = (gi & 63) << 2;
    float ex = ebuf[e];
    int s = src[e], t = tgt[e];
    float4 hv = *(const float4*)(h + (size_t)s*DIM + q);
    redAdd4(num + (size_t)t*DIM + q, ex*hv.x, ex*hv.y, ex*hv.z, ex*hv.w);
}

// ---------------- out = 0.1*num/(den+1e-9) + base --------------------------
__global__ void combine_emb_k(const float* __restrict__ num, const float* __restrict__ den,
                              const float* __restrict__ base, float* __restrict__ out, int n){
    int gi = blockIdx.x*blockDim.x + threadIdx.x;
    if (gi >= n*64) return;
    int node = gi >> 6;
    int j = (gi & 63) << 2;
    float dinv = 0.1f / (den[node] + 1e-9f);
    float4 nu = *(const float4*)(num  + (size_t)node*DIM + j);
    float4 ba = *(const float4*)(base + (size_t)node*DIM + j);
    float4 o;
    o.x = nu.x*dinv + ba.x;
    o.y = nu.y*dinv + ba.y;
    o.z = nu.z*dinv + ba.z;
    o.w = nu.w*dinv + ba.w;
    *(float4*)(out + (size_t)node*DIM + j) = o;
}

// ---------------- precompute dropout-scaled edge weights -------------------
__global__ void wprep_k(const float* __restrict__ vals, const unsigned* __restrict__ m1,
                        const unsigned* __restrict__ m2,
                        float* __restrict__ w1, float* __restrict__ w2, int E){
    int i = blockIdx.x*blockDim.x + threadIdx.x;
    if (i >= E) return;
    float v = vals[i] * (1.0f/0.9f);
    w1[i] = m1[i] ? v : 0.f;
    w2[i] = m2[i] ? v : 0.f;
}

// ---------------- SpMM scatter: dst[rows] += w * src[cols] (vector red) ----
__global__ void spmm_k(const int* __restrict__ rows, const int* __restrict__ cols,
                       const float* __restrict__ w,
                       const float* __restrict__ src, float* __restrict__ dst, int E){
    int gi = blockIdx.x*blockDim.x + threadIdx.x;
    if (gi >= E*64) return;
    int n = gi >> 6;
    float v = w[n];
    if (v == 0.f) return;
    int q = (gi & 63) << 2;
    int c = cols[n], r = rows[n];
    float4 s = *(const float4*)(src + (size_t)c*DIM + q);
    redAdd4(dst + (size_t)r*DIM + q, v*s.x, v*s.y, v*s.z, v*s.w);
}

// ---------------- gather [u, item] rows into [2B, 512] ---------------------
__global__ void gather_k(const float* __restrict__ Eg, const float* __restrict__ Ed,
                         const int* __restrict__ uids, const int* __restrict__ pos,
                         const int* __restrict__ neg, float* __restrict__ out){
    int gi = blockIdx.x*blockDim.x + threadIdx.x;
    if (gi >= 2*B_*128) return;
    int b = gi >> 7;
    int j = (gi & 127) << 2;
    int ub = (b < B_) ? b : b - B_;
    float4 v;
    if (j < DIM) v = *(const float4*)(Eg + (size_t)uids[ub]*DIM + j);
    else {
        int it = (b < B_) ? pos[ub] : neg[ub];
        v = *(const float4*)(Ed + (size_t)it*DIM + (j - DIM));
    }
    *(float4*)(out + (size_t)b*(2*DIM) + j) = v;
}

// ---------------- final linear layer: s = h2 @ W3 + b3 ---------------------
__global__ void score_k(const float* __restrict__ h2, const float* __restrict__ W3,
                        const float* __restrict__ b3, float* __restrict__ s, int R){
    int w = (blockIdx.x*blockDim.x + threadIdx.x) >> 5;
    int lane = threadIdx.x & 31;
    if (w >= R) return;
    const float* hr = h2 + (size_t)w*DIM;
    float acc = 0.f;
    for (int k = lane*4; k < DIM; k += 128){
        float4 hv = *(const float4*)(hr + k);
        float4 wv = *(const float4*)(W3 + k);
        acc += hv.x*wv.x + hv.y*wv.y + hv.z*wv.z + hv.w*wv.w;
    }
    #pragma unroll
    for (int o = 16; o; o >>= 1) acc += __shfl_xor_sync(0xffffffffu, acc, o);
    if (lane == 0) s[w] = acc + b3[0];
}

// ---------------- loss_r reduction -----------------------------------------
__global__ void loss_k(const float* __restrict__ s, int B, double* acc){
    __shared__ double sh[256];
    double local = 0.0;
    for (int i = blockIdx.x*blockDim.x + threadIdx.x; i < B; i += gridDim.x*blockDim.x){
        double ps = s[i], ns = s[B + i];
        local += softplusd(-ps) + softplusd(ns) + softplusd(ns - ps);
    }
    sh[threadIdx.x] = local;
    __syncthreads();
    for (int st = 128; st; st >>= 1){
        if (threadIdx.x < st) sh[threadIdx.x] += sh[threadIdx.x + st];
        __syncthreads();
    }
    if (threadIdx.x == 0) atomicAdd(acc, sh[0]);
}

// ---------------- sum of squares (regularizer) ------------------------------
__global__ void sumsq_k(const float* __restrict__ p, int n, double* acc){
    __shared__ double sh[256];
    double local = 0.0;
    for (int i = blockIdx.x*blockDim.x + threadIdx.x; i < n; i += gridDim.x*blockDim.x){
        double v = p[i];
        local += v*v;
    }
    sh[threadIdx.x] = local;
    __syncthreads();
    for (int st = 128; st; st >>= 1){
        if (threadIdx.x < st) sh[threadIdx.x] += sh[threadIdx.x + st];
        __syncthreads();
    }
    if (threadIdx.x == 0) atomicAdd(acc, sh[0]);
}

// ---------------- final combine --------------------------------------------
__global__ void final_k(const double* lr, const double* reg, float* out, int B){
    double l_r = (*lr) / (double)B;
    out[0] = (float)(1e-7 * (*reg) + l_r);
    out[1] = (float)l_r;
    out[2] = 0.f;
}

// ---------------- launch ----------------------------------------------------
extern "C" void kernel_launch(void* const* d_in, const int* in_sizes, int n_in,
                              void* d_out, int out_size){
    const float* Eg0  = (const float*)d_in[0];
    const float* Ed0  = (const float*)d_in[1];
    const float* attW = (const float*)d_in[2];
    const float* atta = (const float*)d_in[3];
    const float* W1   = (const float*)d_in[6];
    const float* b1   = (const float*)d_in[7];
    const float* W2   = (const float*)d_in[8];
    const float* b2   = (const float*)d_in[9];
    const float* W3   = (const float*)d_in[10];
    const float* b3   = (const float*)d_in[11];
    const float* adj_vals = (const float*)d_in[16];
    const int* uids = (const int*)d_in[17];
    const int* pos  = (const int*)d_in[19];
    const int* neg  = (const int*)d_in[20];
    const int* ge   = (const int*)d_in[21];
    const int* de   = (const int*)d_in[22];
    const int* arows = (const int*)d_in[23];
    const int* acols = (const int*)d_in[24];
    const unsigned* drop1 = (const unsigned*)d_in[25];
    const unsigned* drop2 = (const unsigned*)d_in[26];
    float* out = (float*)d_out;

    float *hg,*hd,*numg,*numd,*Eg0b,*Ed0b,*Eg,*Ed;
    float *alg,*arg,*ald,*ard,*mg,*md,*deng,*dend,*ebg,*ebd,*w1,*w2;
    float *cat,*h1,*h2,*sv;
    double *lr,*reg;
    cudaGetSymbolAddress((void**)&hg,   d_hg);
    cudaGetSymbolAddress((void**)&hd,   d_hd);
    cudaGetSymbolAddress((void**)&numg, d_numg);
    cudaGetSymbolAddress((void**)&numd, d_numd);
    cudaGetSymbolAddress((void**)&Eg0b, d_Eg0b);
    cudaGetSymbolAddress((void**)&Ed0b, d_Ed0b);
    cudaGetSymbolAddress((void**)&Eg,   d_Eg);
    cudaGetSymbolAddress((void**)&Ed,   d_Ed);
    cudaGetSymbolAddress((void**)&alg,  d_alg);
    cudaGetSymbolAddress((void**)&arg,  d_arg_);
    cudaGetSymbolAddress((void**)&ald,  d_ald);
    cudaGetSymbolAddress((void**)&ard,  d_ard);
    cudaGetSymbolAddress((void**)&mg,   d_mg);
    cudaGetSymbolAddress((void**)&md,   d_md);
    cudaGetSymbolAddress((void**)&deng, d_deng);
    cudaGetSymbolAddress((void**)&dend, d_dend);
    cudaGetSymbolAddress((void**)&ebg,  d_ebg);
    cudaGetSymbolAddress((void**)&ebd,  d_ebd);
    cudaGetSymbolAddress((void**)&w1,   d_w1);
    cudaGetSymbolAddress((void**)&w2,   d_w2);
    cudaGetSymbolAddress((void**)&cat,  d_cat);
    cudaGetSymbolAddress((void**)&h1,   d_h1);
    cudaGetSymbolAddress((void**)&h2,   d_h2);
    cudaGetSymbolAddress((void**)&sv,   d_s);
    cudaGetSymbolAddress((void**)&lr,   d_lr_acc);
    cudaGetSymbolAddress((void**)&reg,  d_reg_acc);

    // zero accumulators
    cudaMemsetAsync(numg, 0, sizeof(float)*NN*DIM);
    cudaMemsetAsync(numd, 0, sizeof(float)*NN*DIM);
    cudaMemsetAsync(deng, 0, sizeof(float)*NN);
    cudaMemsetAsync(dend, 0, sizeof(float)*NN);
    cudaMemsetAsync(Eg,   0, sizeof(float)*NN*DIM);
    cudaMemsetAsync(Ed,   0, sizeof(float)*NN*DIM);
    init_k<<<(NN+255)/256, 256>>>(mg, md, NN, lr, reg);
    wprep_k<<<(NNZ_+255)/256, 256>>>(adj_vals, drop1, drop2, w1, w2, NNZ_);

    // h = X @ att_W for both node sets (batched via blockIdx.z)
    sgemm128_k<<<dim3(DIM/128, (NN+127)/128, 2), 256>>>(NN, DIM, DIM,
        Eg0, Ed0, attW, hg, hd, nullptr, 0);

    // attention logits components
    rowdot_k<<<(NN*32+255)/256, 256>>>(hg, atta, alg, arg, NN);
    rowdot_k<<<(NN*32+255)/256, 256>>>(hd, atta, ald, ard, NN);

    // segment max over edges
    edge_max_k<<<(NE_+255)/256, 256>>>(ge, ge+NE_, alg, arg, ebg, mg, NE_);
    edge_max_k<<<(NE_+255)/256, 256>>>(de, de+NE_, ald, ard, ebd, md, NE_);

    // softmax exp + denom
    edge_exp_k<<<(NE_+255)/256, 256>>>(ge+NE_, ebg, mg, deng, NE_);
    edge_exp_k<<<(NE_+255)/256, 256>>>(de+NE_, ebd, md, dend, NE_);

    // softmax numerator accumulation (vector red)
    edge_acc_k<<<(NE_*64)/256, 256>>>(ge, ge+NE_, ebg, hg, numg, NE_);
    edge_acc_k<<<(NE_*64)/256, 256>>>(de, de+NE_, ebd, hd, numd, NE_);

    // E_x0 = 0.1*attn + E_x_0
    combine_emb_k<<<(NN*64)/256, 256>>>(numg, deng, Eg0, Eg0b, NN);
    combine_emb_k<<<(NN*64)/256, 256>>>(numd, dend, Ed0, Ed0b, NN);

    // sparse dropout + SpMM (two independent dropout draws)
    spmm_k<<<(NNZ_*64)/256, 256>>>(arows, acols, w1, Ed0b, Eg, NNZ_);
    spmm_k<<<(NNZ_*64)/256, 256>>>(acols, arows, w2, Eg0b, Ed, NNZ_);

    // gather MLP inputs into one [2B, 512] matrix (pos rows then neg rows)
    gather_k<<<(2*B_*128)/256, 256>>>(Eg, Ed, uids, pos, neg, cat);

    // MLP on concatenated batch
    sgemm128_k<<<dim3(DIM/128, (2*B_)/128, 1), 256>>>(2*B_, DIM, 2*DIM,
        cat, cat, W1, h1, h1, b1, 1);
    sgemm128_k<<<dim3(DIM/128, (2*B_)/128, 1), 256>>>(2*B_, DIM, DIM,
        h1, h1, W2, h2, h2, b2, 1);
    score_k<<<(2*B_*32)/256, 256>>>(h2, W3, b3, sv, 2*B_);

    // losses
    loss_k<<<64, 256>>>(sv, B_, lr);
    for (int i = 0; i < 16; i++){
        int n = in_sizes[i];
        int blocks = (n + 255) / 256;
        if (blocks > 512) blocks = 512;
        sumsq_k<<<blocks, 256>>>((const float*)d_in[i], n, reg);
    }
    final_k<<<1, 1>>>(lr, reg, out, B_);
}

// round 5
// speedup vs baseline: 2.0267x; 1.2549x over previous
#include <cuda_runtime.h>
#include <cuda_bf16.h>
#include <math.h>

#define NN    20000     // N_U == N_I
#define NNP   20096     // padded to multiple of 128
#define DIM   256
#define NNZ_  600000
#define NE_   300000
#define B_    8192

// ---------------- persistent device scratch (no allocations allowed) -------
__device__ float d_hg[NNP*DIM], d_hd[NNP*DIM];
__device__ float d_numg[NN*DIM], d_numd[NN*DIM];
__device__ float d_Eg0b[NN*DIM], d_Ed0b[NN*DIM];
__device__ float d_Eg[NN*DIM], d_Ed[NN*DIM];
__device__ float d_alg[NN], d_arg_[NN], d_ald[NN], d_ard[NN];
__device__ float d_mg[NN], d_md[NN], d_deng[NN], d_dend[NN];
__device__ float d_ebg[NE_], d_ebd[NE_];
__device__ float d_w1[NNZ_], d_w2[NNZ_];
__device__ float d_h2[2*B_*DIM];
__device__ float d_s[2*B_];
__device__ double d_lr_acc, d_reg_acc;
// bf16 scratch
__device__ __nv_bfloat16 d_Eg0h[NNP*DIM], d_Ed0h[NNP*DIM];   // padded rows stay 0
__device__ __nv_bfloat16 d_attWt[DIM*DIM];                    // [N,K] transposed
__device__ __nv_bfloat16 d_W1t[DIM*2*DIM], d_W2t[DIM*DIM];    // transposed
__device__ __nv_bfloat16 d_catb[2*B_*2*DIM], d_h1b[2*B_*DIM];

// ---------------- helpers --------------------------------------------------
__device__ __forceinline__ void atomicMaxF(float* addr, float val){
    int* ia = (int*)addr;
    int old = *ia;
    while (__int_as_float(old) < val){
        int assumed = old;
        old = atomicCAS(ia, assumed, __float_as_int(val));
        if (old == assumed) break;
    }
}

__device__ __forceinline__ void redAdd4(float* p, float a, float b, float c, float d){
    asm volatile("red.global.add.v4.f32 [%0], {%1,%2,%3,%4};"
                 :: "l"(p), "f"(a), "f"(b), "f"(c), "f"(d) : "memory");
}

__device__ __forceinline__ double softplusd(double x){
    return fmax(x, 0.0) + log1p(exp(-fabs(x)));
}

// ---------------- init -----------------------------------------------------
__global__ void init_k(float* mg, float* md, int n, double* lr, double* reg){
    int i = blockIdx.x*blockDim.x + threadIdx.x;
    if (i < n){ mg[i] = -1e30f; md[i] = -1e30f; }
    if (i == 0){ *lr = 0.0; *reg = 0.0; }
}

// ---------------- f32 -> bf16 elementwise ----------------------------------
__global__ void conv_k(const float* __restrict__ in, __nv_bfloat16* __restrict__ out, int n){
    int i = blockIdx.x*blockDim.x + threadIdx.x;
    if (i < n) out[i] = __float2bfloat16(in[i]);
}

// ---------------- f32 [K,N] -> bf16 [N,K] transpose ------------------------
__global__ void convT_k(const float* __restrict__ in, __nv_bfloat16* __restrict__ out,
                        int K, int N){
    int i = blockIdx.x*blockDim.x + threadIdx.x;
    if (i >= K*N) return;
    int k = i / N, n = i % N;
    out[(size_t)n*K + k] = __float2bfloat16(in[i]);
}

// ---------------- bf16 tensor-core GEMM ------------------------------------
// C[M,N] = A[M,K] @ B[K,N]; A bf16 row-major, Bt = B^T bf16 [N,K].
// M % 128 == 0, N % 128 == 0, K % 32 == 0 (buffers pre-padded; no guards).
// Block 128x128x32, 256 threads, 8 warps of 64x32 warp tiles, mma.m16n8k16.
// Output: bf16 (Cb non-null) or f32 (Cf). blockIdx.z selects A0/A1 batch.
__global__ void hgemm_k(int M, int N, int K,
    const __nv_bfloat16* __restrict__ A0, const __nv_bfloat16* __restrict__ A1,
    const __nv_bfloat16* __restrict__ Bt,
    float* __restrict__ Cf0, float* __restrict__ Cf1,
    __nv_bfloat16* __restrict__ Cb0, __nv_bfloat16* __restrict__ Cb1,
    const float* __restrict__ bias, int relu){
    const __nv_bfloat16* A = blockIdx.z ? A1 : A0;
    float* Cf = blockIdx.z ? Cf1 : Cf0;
    __nv_bfloat16* Cb = blockIdx.z ? Cb1 : Cb0;
    __shared__ __nv_bfloat16 As[128][40];   // 40-elem stride: conflict-free frag reads
    __shared__ __nv_bfloat16 Bs[128][40];
    int tid = threadIdx.x;
    int wid = tid >> 5, lane = tid & 31;
    int g = lane >> 2, tg = lane & 3;
    int wm = (wid & 1) * 64, wn = (wid >> 1) * 32;
    int row0 = blockIdx.y * 128, col0 = blockIdx.x * 128;
    float acc[4][4][4] = {};
    for (int k0 = 0; k0 < K; k0 += 32){
        #pragma unroll
        for (int i = 0; i < 2; i++){
            int idx = tid + i*256;
            int r = idx >> 2, c = (idx & 3) * 8;
            *(uint4*)&As[r][c] = *(const uint4*)(A  + (size_t)(row0 + r)*K + k0 + c);
            *(uint4*)&Bs[r][c] = *(const uint4*)(Bt + (size_t)(col0 + r)*K + k0 + c);
        }
        __syncthreads();
        #pragma unroll
        for (int ks = 0; ks < 2; ks++){
            unsigned af[4][4], bfr[4][2];
            #pragma unroll
            for (int mt = 0; mt < 4; mt++){
                int rm = wm + mt*16;
                af[mt][0] = *(unsigned*)&As[rm + g    ][ks*16 + tg*2];
                af[mt][1] = *(unsigned*)&As[rm + g + 8][ks*16 + tg*2];
                af[mt][2] = *(unsigned*)&As[rm + g    ][ks*16 + tg*2 + 8];
                af[mt][3] = *(unsigned*)&As[rm + g + 8][ks*16 + tg*2 + 8];
            }
            #pragma unroll
            for (int nt = 0; nt < 4; nt++){
                int rn = wn + nt*8 + g;
                bfr[nt][0] = *(unsigned*)&Bs[rn][ks*16 + tg*2];
                bfr[nt][1] = *(unsigned*)&Bs[rn][ks*16 + tg*2 + 8];
            }
            #pragma unroll
            for (int mt = 0; mt < 4; mt++)
                #pragma unroll
                for (int nt = 0; nt < 4; nt++)
                    asm volatile(
                        "mma.sync.aligned.m16n8k16.row.col.f32.bf16.bf16.f32 "
                        "{%0,%1,%2,%3},{%4,%5,%6,%7},{%8,%9},{%0,%1,%2,%3};"
                        : "+f"(acc[mt][nt][0]), "+f"(acc[mt][nt][1]),
                          "+f"(acc[mt][nt][2]), "+f"(acc[mt][nt][3])
                        : "r"(af[mt][0]), "r"(af[mt][1]), "r"(af[mt][2]), "r"(af[mt][3]),
                          "r"(bfr[nt][0]), "r"(bfr[nt][1]));
        }
        __syncthreads();
    }
    #pragma unroll
    for (int mt = 0; mt < 4; mt++){
        #pragma unroll
        for (int nt = 0; nt < 4; nt++){
            int col = col0 + wn + nt*8 + tg*2;
            float b0v = 0.f, b1v = 0.f;
            if (bias){ b0v = bias[col]; b1v = bias[col+1]; }
            #pragma unroll
            for (int h = 0; h < 2; h++){
                int row = row0 + wm + mt*16 + g + h*8;
                float v0 = acc[mt][nt][h*2+0] + b0v;
                float v1 = acc[mt][nt][h*2+1] + b1v;
                if (relu){ v0 = fmaxf(v0, 0.f); v1 = fmaxf(v1, 0.f); }
                if (Cb){
                    *(__nv_bfloat162*)(Cb + (size_t)row*N + col) =
                        __floats2bfloat162_rn(v0, v1);
                } else {
                    *(float2*)(Cf + (size_t)row*N + col) = make_float2(v0, v1);
                }
            }
        }
    }
}

// ---------------- per-node dot with attention vector: al=h@a[:D], ar=h@a[D:]
__global__ void rowdot_k(const float* __restrict__ h, const float* __restrict__ a,
                         float* __restrict__ al, float* __restrict__ ar, int n){
    int w = (blockIdx.x*blockDim.x + threadIdx.x) >> 5;
    int lane = threadIdx.x & 31;
    if (w >= n) return;
    const float* hr = h + (size_t)w*DIM;
    float a1 = 0.f, a2 = 0.f;
    for (int k = lane*4; k < DIM; k += 128){
        float4 hv = *(const float4*)(hr + k);
        float4 av = *(const float4*)(a + k);
        float4 bv = *(const float4*)(a + DIM + k);
        a1 += hv.x*av.x + hv.y*av.y + hv.z*av.z + hv.w*av.w;
        a2 += hv.x*bv.x + hv.y*bv.y + hv.z*bv.z + hv.w*bv.w;
    }
    #pragma unroll
    for (int o = 16; o; o >>= 1){
        a1 += __shfl_xor_sync(0xffffffffu, a1, o);
        a2 += __shfl_xor_sync(0xffffffffu, a2, o);
    }
    if (lane == 0){ al[w] = a1; ar[w] = a2; }
}

// ---------------- edge pass 1: e = leaky_relu(al[src]+ar[tgt]); segment max
__global__ void edge_max_k(const int* __restrict__ src, const int* __restrict__ tgt,
                           const float* __restrict__ al, const float* __restrict__ ar,
                           float* __restrict__ ebuf, float* __restrict__ m, int E){
    int i = blockIdx.x*blockDim.x + threadIdx.x;
    if (i >= E) return;
    float x = al[src[i]] + ar[tgt[i]];
    float e = x > 0.f ? x : 0.2f*x;
    ebuf[i] = e;
    atomicMaxF(&m[tgt[i]], e);
}

// ---------------- edge pass 2: ebuf <- exp(e - m[t]); den[t] += ex ----------
__global__ void edge_exp_k(const int* __restrict__ tgt, float* __restrict__ ebuf,
                           const float* __restrict__ m, float* __restrict__ den, int E){
    int i = blockIdx.x*blockDim.x + threadIdx.x;
    if (i >= E) return;
    int t = tgt[i];
    float ex = __expf(ebuf[i] - m[t]);
    ebuf[i] = ex;
    atomicAdd(&den[t], ex);
}

// ---------------- edge pass 3: num[tgt] += ex * h[src] (vector red) --------
__global__ void edge_acc_k(const int* __restrict__ src, const int* __restrict__ tgt,
                           const float* __restrict__ ebuf,
                           const float* __restrict__ h, float* __restrict__ num, int E){
    int gi = blockIdx.x*blockDim.x + threadIdx.x;
    if (gi >= E*64) return;
    int e = gi >> 6;
    int q = (gi & 63) << 2;
    float ex = ebuf[e];
    int s = src[e], t = tgt[e];
    float4 hv = *(const float4*)(h + (size_t)s*DIM + q);
    redAdd4(num + (size_t)t*DIM + q, ex*hv.x, ex*hv.y, ex*hv.z, ex*hv.w);
}

// ---------------- out = 0.1*num/(den+1e-9) + base --------------------------
__global__ void combine_emb_k(const float* __restrict__ num, const float* __restrict__ den,
                              const float* __restrict__ base, float* __restrict__ out, int n){
    int gi = blockIdx.x*blockDim.x + threadIdx.x;
    if (gi >= n*64) return;
    int node = gi >> 6;
    int j = (gi & 63) << 2;
    float dinv = 0.1f / (den[node] + 1e-9f);
    float4 nu = *(const float4*)(num  + (size_t)node*DIM + j);
    float4 ba = *(const float4*)(base + (size_t)node*DIM + j);
    float4 o;
    o.x = nu.x*dinv + ba.x;
    o.y = nu.y*dinv + ba.y;
    o.z = nu.z*dinv + ba.z;
    o.w = nu.w*dinv + ba.w;
    *(float4*)(out + (size_t)node*DIM + j) = o;
}

// ---------------- precompute dropout-scaled edge weights -------------------
__global__ void wprep_k(const float* __restrict__ vals, const unsigned* __restrict__ m1,
                        const unsigned* __restrict__ m2,
                        float* __restrict__ w1, float* __restrict__ w2, int E){
    int i = blockIdx.x*blockDim.x + threadIdx.x;
    if (i >= E) return;
    float v = vals[i] * (1.0f/0.9f);
    w1[i] = m1[i] ? v : 0.f;
    w2[i] = m2[i] ? v : 0.f;
}

// ---------------- SpMM scatter: dst[rows] += w * src[cols] (vector red) ----
__global__ void spmm_k(const int* __restrict__ rows, const int* __restrict__ cols,
                       const float* __restrict__ w,
                       const float* __restrict__ src, float* __restrict__ dst, int E){
    int gi = blockIdx.x*blockDim.x + threadIdx.x;
    if (gi >= E*64) return;
    int n = gi >> 6;
    float v = w[n];
    if (v == 0.f) return;
    int q = (gi & 63) << 2;
    int c = cols[n], r = rows[n];
    float4 s = *(const float4*)(src + (size_t)c*DIM + q);
    redAdd4(dst + (size_t)r*DIM + q, v*s.x, v*s.y, v*s.z, v*s.w);
}

// ---------------- gather [u, item] rows into [2B, 512] bf16 ----------------
__global__ void gatherb_k(const float* __restrict__ Eg, const float* __restrict__ Ed,
                          const int* __restrict__ uids, const int* __restrict__ pos,
                          const int* __restrict__ neg, __nv_bfloat16* __restrict__ out){
    int gi = blockIdx.x*blockDim.x + threadIdx.x;
    if (gi >= 2*B_*128) return;
    int b = gi >> 7;
    int j = (gi & 127) << 2;
    int ub = (b < B_) ? b : b - B_;
    float4 v;
    if (j < DIM) v = *(const float4*)(Eg + (size_t)uids[ub]*DIM + j);
    else {
        int it = (b < B_) ? pos[ub] : neg[ub];
        v = *(const float4*)(Ed + (size_t)it*DIM + (j - DIM));
    }
    __nv_bfloat162 lo = __floats2bfloat162_rn(v.x, v.y);
    __nv_bfloat162 hi = __floats2bfloat162_rn(v.z, v.w);
    uint2 packed;
    packed.x = *(unsigned*)&lo;
    packed.y = *(unsigned*)&hi;
    *(uint2*)(out + (size_t)b*(2*DIM) + j) = packed;
}

// ---------------- final linear layer: s = h2 @ W3 + b3 ---------------------
__global__ void score_k(const float* __restrict__ h2, const float* __restrict__ W3,
                        const float* __restrict__ b3, float* __restrict__ s, int R){
    int w = (blockIdx.x*blockDim.x + threadIdx.x) >> 5;
    int lane = threadIdx.x & 31;
    if (w >= R) return;
    const float* hr = h2 + (size_t)w*DIM;
    float acc = 0.f;
    for (int k = lane*4; k < DIM; k += 128){
        float4 hv = *(const float4*)(hr + k);
        float4 wv = *(const float4*)(W3 + k);
        acc += hv.x*wv.x + hv.y*wv.y + hv.z*wv.z + hv.w*wv.w;
    }
    #pragma unroll
    for (int o = 16; o; o >>= 1) acc += __shfl_xor_sync(0xffffffffu, acc, o);
    if (lane == 0) s[w] = acc + b3[0];
}

// ---------------- loss_r reduction -----------------------------------------
__global__ void loss_k(const float* __restrict__ s, int B, double* acc){
    __shared__ double sh[256];
    double local = 0.0;
    for (int i = blockIdx.x*blockDim.x + threadIdx.x; i < B; i += gridDim.x*blockDim.x){
        double ps = s[i], ns = s[B + i];
        local += softplusd(-ps) + softplusd(ns) + softplusd(ns - ps);
    }
    sh[threadIdx.x] = local;
    __syncthreads();
    for (int st = 128; st; st >>= 1){
        if (threadIdx.x < st) sh[threadIdx.x] += sh[threadIdx.x + st];
        __syncthreads();
    }
    if (threadIdx.x == 0) atomicAdd(acc, sh[0]);
}

// ---------------- sum of squares (regularizer) ------------------------------
__global__ void sumsq_k(const float* __restrict__ p, int n, double* acc){
    __shared__ double sh[256];
    double local = 0.0;
    for (int i = blockIdx.x*blockDim.x + threadIdx.x; i < n; i += gridDim.x*blockDim.x){
        double v = p[i];
        local += v*v;
    }
    sh[threadIdx.x] = local;
    __syncthreads();
    for (int st = 128; st; st >>= 1){
        if (threadIdx.x < st) sh[threadIdx.x] += sh[threadIdx.x + st];
        __syncthreads();
    }
    if (threadIdx.x == 0) atomicAdd(acc, sh[0]);
}

// ---------------- final combine --------------------------------------------
__global__ void final_k(const double* lr, const double* reg, float* out, int B){
    double l_r = (*lr) / (double)B;
    out[0] = (float)(1e-7 * (*reg) + l_r);
    out[1] = (float)l_r;
    out[2] = 0.f;
}

// ---------------- launch ----------------------------------------------------
extern "C" void kernel_launch(void* const* d_in, const int* in_sizes, int n_in,
                              void* d_out, int out_size){
    const float* Eg0  = (const float*)d_in[0];
    const float* Ed0  = (const float*)d_in[1];
    const float* attW = (const float*)d_in[2];
    const float* atta = (const float*)d_in[3];
    const float* W1   = (const float*)d_in[6];
    const float* b1   = (const float*)d_in[7];
    const float* W2   = (const float*)d_in[8];
    const float* b2   = (const float*)d_in[9];
    const float* W3   = (const float*)d_in[10];
    const float* b3   = (const float*)d_in[11];
    const float* adj_vals = (const float*)d_in[16];
    const int* uids = (const int*)d_in[17];
    const int* pos  = (const int*)d_in[19];
    const int* neg  = (const int*)d_in[20];
    const int* ge   = (const int*)d_in[21];
    const int* de   = (const int*)d_in[22];
    const int* arows = (const int*)d_in[23];
    const int* acols = (const int*)d_in[24];
    const unsigned* drop1 = (const unsigned*)d_in[25];
    const unsigned* drop2 = (const unsigned*)d_in[26];
    float* out = (float*)d_out;

    float *hg,*hd,*numg,*numd,*Eg0b,*Ed0b,*Eg,*Ed;
    float *alg,*arg,*ald,*ard,*mg,*md,*deng,*dend,*ebg,*ebd,*w1,*w2;
    float *h2,*sv;
    __nv_bfloat16 *Eg0h,*Ed0h,*attWt,*W1t,*W2t,*catb,*h1b;
    double *lr,*reg;
    cudaGetSymbolAddress((void**)&hg,   d_hg);
    cudaGetSymbolAddress((void**)&hd,   d_hd);
    cudaGetSymbolAddress((void**)&numg, d_numg);
    cudaGetSymbolAddress((void**)&numd, d_numd);
    cudaGetSymbolAddress((void**)&Eg0b, d_Eg0b);
    cudaGetSymbolAddress((void**)&Ed0b, d_Ed0b);
    cudaGetSymbolAddress((void**)&Eg,   d_Eg);
    cudaGetSymbolAddress((void**)&Ed,   d_Ed);
    cudaGetSymbolAddress((void**)&alg,  d_alg);
    cudaGetSymbolAddress((void**)&arg,  d_arg_);
    cudaGetSymbolAddress((void**)&ald,  d_ald);
    cudaGetSymbolAddress((void**)&ard,  d_ard);
    cudaGetSymbolAddress((void**)&mg,   d_mg);
    cudaGetSymbolAddress((void**)&md,   d_md);
    cudaGetSymbolAddress((void**)&deng, d_deng);
    cudaGetSymbolAddress((void**)&dend, d_dend);
    cudaGetSymbolAddress((void**)&ebg,  d_ebg);
    cudaGetSymbolAddress((void**)&ebd,  d_ebd);
    cudaGetSymbolAddress((void**)&w1,   d_w1);
    cudaGetSymbolAddress((void**)&w2,   d_w2);
    cudaGetSymbolAddress((void**)&h2,   d_h2);
    cudaGetSymbolAddress((void**)&sv,   d_s);
    cudaGetSymbolAddress((void**)&Eg0h, d_Eg0h);
    cudaGetSymbolAddress((void**)&Ed0h, d_Ed0h);
    cudaGetSymbolAddress((void**)&attWt,d_attWt);
    cudaGetSymbolAddress((void**)&W1t,  d_W1t);
    cudaGetSymbolAddress((void**)&W2t,  d_W2t);
    cudaGetSymbolAddress((void**)&catb, d_catb);
    cudaGetSymbolAddress((void**)&h1b,  d_h1b);
    cudaGetSymbolAddress((void**)&lr,   d_lr_acc);
    cudaGetSymbolAddress((void**)&reg,  d_reg_acc);

    // zero accumulators
    cudaMemsetAsync(numg, 0, sizeof(float)*NN*DIM);
    cudaMemsetAsync(numd, 0, sizeof(float)*NN*DIM);
    cudaMemsetAsync(deng, 0, sizeof(float)*NN);
    cudaMemsetAsync(dend, 0, sizeof(float)*NN);
    cudaMemsetAsync(Eg,   0, sizeof(float)*NN*DIM);
    cudaMemsetAsync(Ed,   0, sizeof(float)*NN*DIM);
    init_k<<<(NN+255)/256, 256>>>(mg, md, NN, lr, reg);
    wprep_k<<<(NNZ_+255)/256, 256>>>(adj_vals, drop1, drop2, w1, w2, NNZ_);

    // bf16 conversions (weights transposed to [N,K]); padded rows remain zero
    conv_k<<<(NN*DIM+255)/256, 256>>>(Eg0, Eg0h, NN*DIM);
    conv_k<<<(NN*DIM+255)/256, 256>>>(Ed0, Ed0h, NN*DIM);
    convT_k<<<(DIM*DIM+255)/256, 256>>>(attW, attWt, DIM, DIM);
    convT_k<<<(2*DIM*DIM+255)/256, 256>>>(W1, W1t, 2*DIM, DIM);
    convT_k<<<(DIM*DIM+255)/256, 256>>>(W2, W2t, DIM, DIM);

    // h = X @ att_W for both node sets (tensor cores, z-batched)
    hgemm_k<<<dim3(DIM/128, NNP/128, 2), 256>>>(NNP, DIM, DIM,
        Eg0h, Ed0h, attWt, hg, hd, nullptr, nullptr, nullptr, 0);

    // attention logits components
    rowdot_k<<<(NN*32+255)/256, 256>>>(hg, atta, alg, arg, NN);
    rowdot_k<<<(NN*32+255)/256, 256>>>(hd, atta, ald, ard, NN);

    // segment max over edges
    edge_max_k<<<(NE_+255)/256, 256>>>(ge, ge+NE_, alg, arg, ebg, mg, NE_);
    edge_max_k<<<(NE_+255)/256, 256>>>(de, de+NE_, ald, ard, ebd, md, NE_);

    // softmax exp + denom
    edge_exp_k<<<(NE_+255)/256, 256>>>(ge+NE_, ebg, mg, deng, NE_);
    edge_exp_k<<<(NE_+255)/256, 256>>>(de+NE_, ebd, md, dend, NE_);

    // softmax numerator accumulation (vector red)
    edge_acc_k<<<(NE_*64)/256, 256>>>(ge, ge+NE_, ebg, hg, numg, NE_);
    edge_acc_k<<<(NE_*64)/256, 256>>>(de, de+NE_, ebd, hd, numd, NE_);

    // E_x0 = 0.1*attn + E_x_0
    combine_emb_k<<<(NN*64)/256, 256>>>(numg, deng, Eg0, Eg0b, NN);
    combine_emb_k<<<(NN*64)/256, 256>>>(numd, dend, Ed0, Ed0b, NN);

    // sparse dropout + SpMM (two independent dropout draws)
    spmm_k<<<(NNZ_*64)/256, 256>>>(arows, acols, w1, Ed0b, Eg, NNZ_);
    spmm_k<<<(NNZ_*64)/256, 256>>>(acols, arows, w2, Eg0b, Ed, NNZ_);

    // gather MLP inputs into one [2B, 512] bf16 matrix (pos then neg)
    gatherb_k<<<(2*B_*128)/256, 256>>>(Eg, Ed, uids, pos, neg, catb);

    // MLP on concatenated batch (tensor cores)
    hgemm_k<<<dim3(DIM/128, (2*B_)/128, 1), 256>>>(2*B_, DIM, 2*DIM,
        catb, catb, W1t, nullptr, nullptr, h1b, h1b, b1, 1);
    hgemm_k<<<dim3(DIM/128, (2*B_)/128, 1), 256>>>(2*B_, DIM, DIM,
        h1b, h1b, W2t, h2, h2, nullptr, nullptr, b2, 1);
    score_k<<<(2*B_*32)/256, 256>>>(h2, W3, b3, sv, 2*B_);

    // losses
    loss_k<<<64, 256>>>(sv, B_, lr);
    for (int i = 0; i < 16; i++){
        int n = in_sizes[i];
        int blocks = (n + 255) / 256;
        if (blocks > 512) blocks = 512;
        sumsq_k<<<blocks, 256>>>((const float*)d_in[i], n, reg);
    }
    final_k<<<1, 1>>>(lr, reg, out, B_);
}

// round 7
// speedup vs baseline: 3.4841x; 1.7191x over previous
#include <cuda_runtime.h>
#include <cuda_bf16.h>
#include <math.h>

#define NN    20000     // N_U == N_I
#define NNP   20096     // padded to multiple of 128
#define DIM   256
#define NNZ_  600000
#define NE_   300000
#define B_    8192

// ---------------- persistent device scratch (no allocations allowed) -------
__device__ float d_hg[NNP*DIM], d_hd[NNP*DIM];
__device__ float d_Eg0b[NN*DIM], d_Ed0b[NN*DIM];
__device__ float d_Eg[NN*DIM], d_Ed[NN*DIM];
__device__ float d_alg[NN], d_arg_[NN], d_ald[NN], d_ard[NN];
__device__ float d_w1[NNZ_], d_w2[NNZ_];
__device__ float d_h2[2*B_*DIM];
__device__ float d_s[2*B_];
__device__ double d_lr_acc, d_reg_acc;
// CSR structures (rebuilt every launch)
__device__ int   d_ctl[8*(NN+1)];            // 4 counters + 4 cursors
__device__ int   d_off[4*(NN+1)];            // 4 offset arrays
__device__ int   d_payg[NE_], d_payd[NE_];   // attention payload: src node
__device__ int   d_pc1[NNZ_], d_pc2[NNZ_];   // spmm payload: col
__device__ float d_pw1[NNZ_], d_pw2[NNZ_];   // spmm payload: weight
// bf16 scratch
__device__ __nv_bfloat16 d_Eg0h[NNP*DIM], d_Ed0h[NNP*DIM];   // padded rows stay 0
__device__ __nv_bfloat16 d_attWt[DIM*DIM];                    // [N,K] transposed
__device__ __nv_bfloat16 d_W1t[DIM*2*DIM], d_W2t[DIM*DIM];    // transposed
__device__ __nv_bfloat16 d_catb[2*B_*2*DIM], d_h1b[2*B_*DIM];

struct ScanArgs { const int* cnt[4]; int* off[4]; };
struct P16 { const float* p[16]; int n[16]; };

__device__ __forceinline__ double softplusd(double x){
    return fmax(x, 0.0) + log1p(exp(-fabs(x)));
}

// ---------------- f32 -> bf16, both embedding tables, vectorized ----------
__global__ void conv2_k(const float* __restrict__ a, const float* __restrict__ b,
                        __nv_bfloat16* __restrict__ oa, __nv_bfloat16* __restrict__ ob,
                        int nvec){
    int i = blockIdx.x*blockDim.x + threadIdx.x;
    if (i >= 2*nvec) return;
    const float* src; __nv_bfloat16* dst; int j;
    if (i < nvec){ src = a; dst = oa; j = i; }
    else         { src = b; dst = ob; j = i - nvec; }
    float4 v = ((const float4*)src)[j];
    __nv_bfloat162 lo = __floats2bfloat162_rn(v.x, v.y);
    __nv_bfloat162 hi = __floats2bfloat162_rn(v.z, v.w);
    uint2 pk; pk.x = *(unsigned*)&lo; pk.y = *(unsigned*)&hi;
    ((uint2*)dst)[j] = pk;
}

// ---------------- f32 [K,N] -> bf16 [N,K] transpose ------------------------
__global__ void convT_k(const float* __restrict__ in, __nv_bfloat16* __restrict__ out,
                        int K, int N){
    int i = blockIdx.x*blockDim.x + threadIdx.x;
    if (i >= K*N) return;
    int k = i / N, n = i % N;
    out[(size_t)n*K + k] = __float2bfloat16(in[i]);
}

// ---------------- dropout-scaled edge weights ------------------------------
__global__ void wprep_k(const float* __restrict__ vals, const unsigned* __restrict__ m1,
                        const unsigned* __restrict__ m2,
                        float* __restrict__ w1, float* __restrict__ w2, int E){
    int i = blockIdx.x*blockDim.x + threadIdx.x;
    if (i >= E) return;
    float v = vals[i] * (1.0f/0.9f);
    w1[i] = m1[i] ? v : 0.f;
    w2[i] = m2[i] ? v : 0.f;
}

// ---------------- CSR build: histogram / scan / scatter --------------------
__global__ void hist_k(const int* __restrict__ keys, int* __restrict__ cnt, int E){
    int i = blockIdx.x*blockDim.x + threadIdx.x;
    if (i < E) atomicAdd(&cnt[keys[i]], 1);
}

// one block per array; 256 threads; exclusive scan of n counts -> off[0..n]
__global__ void scan4_k(ScanArgs a, int n){
    const int* cnt = a.cnt[blockIdx.x];
    int* off = a.off[blockIdx.x];
    __shared__ int part[256];
    int tid = threadIdx.x;
    int per = (n + 255) / 256;
    int st = tid*per, en = st + per; if (en > n) en = n;
    int s = 0;
    for (int i = st; i < en; i++) s += cnt[i];
    part[tid] = s;
    __syncthreads();
    for (int o = 1; o < 256; o <<= 1){
        int v = (tid >= o) ? part[tid - o] : 0;
        __syncthreads();
        part[tid] += v;
        __syncthreads();
    }
    int base = tid ? part[tid - 1] : 0;
    for (int i = st; i < en; i++){ off[i] = base; base += cnt[i]; }
    if (tid == 255) off[n] = part[255];
}

__global__ void build_att_k(const int* __restrict__ src, const int* __restrict__ tgt,
                            int* __restrict__ cursor, const int* __restrict__ off,
                            int* __restrict__ pay, int E){
    int i = blockIdx.x*blockDim.x + threadIdx.x;
    if (i >= E) return;
    int t = tgt[i];
    int p = atomicAdd(&cursor[t], 1);
    pay[off[t] + p] = src[i];
}

__global__ void build_adj_k(const int* __restrict__ keys, const int* __restrict__ other,
                            const float* __restrict__ w,
                            int* __restrict__ cursor, const int* __restrict__ off,
                            int* __restrict__ pcol, float* __restrict__ pw, int E){
    int i = blockIdx.x*blockDim.x + threadIdx.x;
    if (i >= E) return;
    int k = keys[i];
    int p = atomicAdd(&cursor[k], 1);
    int slot = off[k] + p;
    pcol[slot] = other[i];
    pw[slot]   = w[i];
}

// ---------------- bf16 tensor-core GEMM ------------------------------------
// C[M,N] = A[M,K] @ B[K,N]; A bf16 row-major, Bt = B^T bf16 [N,K].
// M % 128 == 0, N % 128 == 0, K % 32 == 0 (padded; no guards).
__global__ void hgemm_k(int M, int N, int K,
    const __nv_bfloat16* __restrict__ A0, const __nv_bfloat16* __restrict__ A1,
    const __nv_bfloat16* __restrict__ Bt,
    float* __restrict__ Cf0, float* __restrict__ Cf1,
    __nv_bfloat16* __restrict__ Cb0, __nv_bfloat16* __restrict__ Cb1,
    const float* __restrict__ bias, int relu){
    const __nv_bfloat16* A = blockIdx.z ? A1 : A0;
    float* Cf = blockIdx.z ? Cf1 : Cf0;
    __nv_bfloat16* Cb = blockIdx.z ? Cb1 : Cb0;
    __shared__ __nv_bfloat16 As[128][40];
    __shared__ __nv_bfloat16 Bs[128][40];
    int tid = threadIdx.x;
    int wid = tid >> 5, lane = tid & 31;
    int g = lane >> 2, tg = lane & 3;
    int wm = (wid & 1) * 64, wn = (wid >> 1) * 32;
    int row0 = blockIdx.y * 128, col0 = blockIdx.x * 128;
    float acc[4][4][4] = {};
    for (int k0 = 0; k0 < K; k0 += 32){
        #pragma unroll
        for (int i = 0; i < 2; i++){
            int idx = tid + i*256;
            int r = idx >> 2, c = (idx & 3) * 8;
            *(uint4*)&As[r][c] = *(const uint4*)(A  + (size_t)(row0 + r)*K + k0 + c);
            *(uint4*)&Bs[r][c] = *(const uint4*)(Bt + (size_t)(col0 + r)*K + k0 + c);
        }
        __syncthreads();
        #pragma unroll
        for (int ks = 0; ks < 2; ks++){
            unsigned af[4][4], bfr[4][2];
            #pragma unroll
            for (int mt = 0; mt < 4; mt++){
                int rm = wm + mt*16;
                af[mt][0] = *(unsigned*)&As[rm + g    ][ks*16 + tg*2];
                af[mt][1] = *(unsigned*)&As[rm + g + 8][ks*16 + tg*2];
                af[mt][2] = *(unsigned*)&As[rm + g    ][ks*16 + tg*2 + 8];
                af[mt][3] = *(unsigned*)&As[rm + g + 8][ks*16 + tg*2 + 8];
            }
            #pragma unroll
            for (int nt = 0; nt < 4; nt++){
                int rn = wn + nt*8 + g;
                bfr[nt][0] = *(unsigned*)&Bs[rn][ks*16 + tg*2];
                bfr[nt][1] = *(unsigned*)&Bs[rn][ks*16 + tg*2 + 8];
            }
            #pragma unroll
            for (int mt = 0; mt < 4; mt++)
                #pragma unroll
                for (int nt = 0; nt < 4; nt++)
                    asm volatile(
                        "mma.sync.aligned.m16n8k16.row.col.f32.bf16.bf16.f32 "
                        "{%0,%1,%2,%3},{%4,%5,%6,%7},{%8,%9},{%0,%1,%2,%3};"
                        : "+f"(acc[mt][nt][0]), "+f"(acc[mt][nt][1]),
                          "+f"(acc[mt][nt][2]), "+f"(acc[mt][nt][3])
                        : "r"(af[mt][0]), "r"(af[mt][1]), "r"(af[mt][2]), "r"(af[mt][3]),
                          "r"(bfr[nt][0]), "r"(bfr[nt][1]));
        }
        __syncthreads();
    }
    #pragma unroll
    for (int mt = 0; mt < 4; mt++){
        #pragma unroll
        for (int nt = 0; nt < 4; nt++){
            int col = col0 + wn + nt*8 + tg*2;
            float b0v = 0.f, b1v = 0.f;
            if (bias){ b0v = bias[col]; b1v = bias[col+1]; }
            #pragma unroll
            for (int h = 0; h < 2; h++){
                int row = row0 + wm + mt*16 + g + h*8;
                float v0 = acc[mt][nt][h*2+0] + b0v;
                float v1 = acc[mt][nt][h*2+1] + b1v;
                if (relu){ v0 = fmaxf(v0, 0.f); v1 = fmaxf(v1, 0.f); }
                if (Cb){
                    *(__nv_bfloat162*)(Cb + (size_t)row*N + col) =
                        __floats2bfloat162_rn(v0, v1);
                } else {
                    *(float2*)(Cf + (size_t)row*N + col) = make_float2(v0, v1);
                }
            }
        }
    }
}

// ---------------- per-node attention dots, both graphs (z-batched) ---------
__global__ void rowdot2_k(const float* __restrict__ hg, const float* __restrict__ hd,
                          const float* __restrict__ a,
                          float* __restrict__ alg, float* __restrict__ arg,
                          float* __restrict__ ald, float* __restrict__ ard, int n){
    const float* h = blockIdx.z ? hd : hg;
    float* al = blockIdx.z ? ald : alg;
    float* ar = blockIdx.z ? ard : arg;
    int w = (blockIdx.x*blockDim.x + threadIdx.x) >> 5;
    int lane = threadIdx.x & 31;
    if (w >= n) return;
    const float* hr = h + (size_t)w*DIM;
    float a1 = 0.f, a2 = 0.f;
    for (int k = lane*4; k < DIM; k += 128){
        float4 hv = *(const float4*)(hr + k);
        float4 av = *(const float4*)(a + k);
        float4 bv = *(const float4*)(a + DIM + k);
        a1 += hv.x*av.x + hv.y*av.y + hv.z*av.z + hv.w*av.w;
        a2 += hv.x*bv.x + hv.y*bv.y + hv.z*bv.z + hv.w*bv.w;
    }
    #pragma unroll
    for (int o = 16; o; o >>= 1){
        a1 += __shfl_xor_sync(0xffffffffu, a1, o);
        a2 += __shfl_xor_sync(0xffffffffu, a2, o);
    }
    if (lane == 0){ al[w] = a1; ar[w] = a2; }
}

// ---------------- fused CSR attention: softmax + aggregate + combine -------
// out[t] = 0.1 * (sum_e ex_e * h[src_e]) / (sum ex + 1e-9) + base[t]
__global__ void att_csr_k(const int* __restrict__ off, const int* __restrict__ pay,
                          const float* __restrict__ al, const float* __restrict__ ar,
                          const float* __restrict__ h, const float* __restrict__ base,
                          float* __restrict__ out, int n){
    int t = (blockIdx.x*blockDim.x + threadIdx.x) >> 5;
    int lane = threadIdx.x & 31;
    if (t >= n) return;
    int s0 = off[t], s1 = off[t+1];
    float art = ar[t];
    float m = -1e30f;
    for (int i = s0 + lane; i < s1; i += 32){
        float x = al[pay[i]] + art;
        x = x > 0.f ? x : 0.2f*x;
        m = fmaxf(m, x);
    }
    #pragma unroll
    for (int o = 16; o; o >>= 1) m = fmaxf(m, __shfl_xor_sync(0xffffffffu, m, o));
    float den = 0.f;
    float4 a0 = {0,0,0,0}, a1 = {0,0,0,0};
    const float4* hb = (const float4*)h;
    for (int i = s0; i < s1; i++){
        int s = pay[i];
        float x = al[s] + art;
        x = x > 0.f ? x : 0.2f*x;
        float ex = __expf(x - m);
        den += ex;
        const float4* hr = hb + (size_t)s*(DIM/4) + lane*2;
        float4 v0 = hr[0], v1 = hr[1];
        a0.x += ex*v0.x; a0.y += ex*v0.y; a0.z += ex*v0.z; a0.w += ex*v0.w;
        a1.x += ex*v1.x; a1.y += ex*v1.y; a1.z += ex*v1.z; a1.w += ex*v1.w;
    }
    float dinv = 0.1f / (den + 1e-9f);
    const float4* bp = (const float4*)base + (size_t)t*(DIM/4) + lane*2;
    float4* op = (float4*)out + (size_t)t*(DIM/4) + lane*2;
    float4 b0 = bp[0], b1 = bp[1], o0, o1;
    o0.x = a0.x*dinv + b0.x; o0.y = a0.y*dinv + b0.y;
    o0.z = a0.z*dinv + b0.z; o0.w = a0.w*dinv + b0.w;
    o1.x = a1.x*dinv + b1.x; o1.y = a1.y*dinv + b1.y;
    o1.z = a1.z*dinv + b1.z; o1.w = a1.w*dinv + b1.w;
    op[0] = o0; op[1] = o1;
}

// ---------------- CSR SpMM: dst[r] = sum_e w_e * src[col_e] ----------------
__global__ void spmm_csr_k(const int* __restrict__ off, const int* __restrict__ pcol,
                           const float* __restrict__ pw,
                           const float* __restrict__ src, float* __restrict__ dst, int n){
    int r = (blockIdx.x*blockDim.x + threadIdx.x) >> 5;
    int lane = threadIdx.x & 31;
    if (r >= n) return;
    int s0 = off[r], s1 = off[r+1];
    float4 a0 = {0,0,0,0}, a1 = {0,0,0,0};
    const float4* sb = (const float4*)src;
    for (int i = s0; i < s1; i++){
        float v = pw[i];
        if (v == 0.f) continue;
        int c = pcol[i];
        const float4* sr = sb + (size_t)c*(DIM/4) + lane*2;
        float4 v0 = sr[0], v1 = sr[1];
        a0.x += v*v0.x; a0.y += v*v0.y; a0.z += v*v0.z; a0.w += v*v0.w;
        a1.x += v*v1.x; a1.y += v*v1.y; a1.z += v*v1.z; a1.w += v*v1.w;
    }
    float4* op = (float4*)dst + (size_t)r*(DIM/4) + lane*2;
    op[0] = a0; op[1] = a1;
}

// ---------------- gather [u, item] rows into [2B, 512] bf16 ----------------
__global__ void gatherb_k(const float* __restrict__ Eg, const float* __restrict__ Ed,
                          const int* __restrict__ uids, const int* __restrict__ pos,
                          const int* __restrict__ neg, __nv_bfloat16* __restrict__ out){
    int gi = blockIdx.x*blockDim.x + threadIdx.x;
    if (gi >= 2*B_*128) return;
    int b = gi >> 7;
    int j = (gi & 127) << 2;
    int ub = (b < B_) ? b : b - B_;
    float4 v;
    if (j < DIM) v = *(const float4*)(Eg + (size_t)uids[ub]*DIM + j);
    else {
        int it = (b < B_) ? pos[ub] : neg[ub];
        v = *(const float4*)(Ed + (size_t)it*DIM + (j - DIM));
    }
    __nv_bfloat162 lo = __floats2bfloat162_rn(v.x, v.y);
    __nv_bfloat162 hi = __floats2bfloat162_rn(v.z, v.w);
    uint2 packed;
    packed.x = *(unsigned*)&lo;
    packed.y = *(unsigned*)&hi;
    *(uint2*)(out + (size_t)b*(2*DIM) + j) = packed;
}

// ---------------- final linear layer: s = h2 @ W3 + b3 ---------------------
__global__ void score_k(const float* __restrict__ h2, const float* __restrict__ W3,
                        const float* __restrict__ b3, float* __restrict__ s, int R){
    int w = (blockIdx.x*blockDim.x + threadIdx.x) >> 5;
    int lane = threadIdx.x & 31;
    if (w >= R) return;
    const float* hr = h2 + (size_t)w*DIM;
    float acc = 0.f;
    for (int k = lane*4; k < DIM; k += 128){
        float4 hv = *(const float4*)(hr + k);
        float4 wv = *(const float4*)(W3 + k);
        acc += hv.x*wv.x + hv.y*wv.y + hv.z*wv.z + hv.w*wv.w;
    }
    #pragma unroll
    for (int o = 16; o; o >>= 1) acc += __shfl_xor_sync(0xffffffffu, acc, o);
    if (lane == 0) s[w] = acc + b3[0];
}

// ---------------- loss_r reduction -----------------------------------------
__global__ void loss_k(const float* __restrict__ s, int B, double* acc){
    __shared__ double sh[256];
    double local = 0.0;
    for (int i = blockIdx.x*blockDim.x + threadIdx.x; i < B; i += gridDim.x*blockDim.x){
        double ps = s[i], ns = s[B + i];
        local += softplusd(-ps) + softplusd(ns) + softplusd(ns - ps);
    }
    sh[threadIdx.x] = local;
    __syncthreads();
    for (int st = 128; st; st >>= 1){
        if (threadIdx.x < st) sh[threadIdx.x] += sh[threadIdx.x + st];
        __syncthreads();
    }
    if (threadIdx.x == 0) atomicAdd(acc, sh[0]);
}

// ---------------- sum of squares over all 16 params, one launch ------------
__global__ void sumsq16_k(P16 a, double* acc){
    const float* p = a.p[blockIdx.y];
    int n = a.n[blockIdx.y];
    __shared__ double sh[256];
    double local = 0.0;
    for (int i = blockIdx.x*blockDim.x + threadIdx.x; i < n; i += gridDim.x*blockDim.x){
        double v = p[i];
        local += v*v;
    }
    sh[threadIdx.x] = local;
    __syncthreads();
    for (int st = 128; st; st >>= 1){
        if (threadIdx.x < st) sh[threadIdx.x] += sh[threadIdx.x + st];
        __syncthreads();
    }
    if (threadIdx.x == 0 && sh[0] != 0.0) atomicAdd(acc, sh[0]);
}

// ---------------- final combine --------------------------------------------
__global__ void final_k(const double* lr, const double* reg, float* out, int B){
    double l_r = (*lr) / (double)B;
    out[0] = (float)(1e-7 * (*reg) + l_r);
    out[1] = (float)l_r;
    out[2] = 0.f;
}

// ---------------- launch ----------------------------------------------------
extern "C" void kernel_launch(void* const* d_in, const int* in_sizes, int n_in,
                              void* d_out, int out_size){
    const float* Eg0  = (const float*)d_in[0];
    const float* Ed0  = (const float*)d_in[1];
    const float* attW = (const float*)d_in[2];
    const float* atta = (const float*)d_in[3];
    const float* W1   = (const float*)d_in[6];
    const float* b1   = (const float*)d_in[7];
    const float* W2   = (const float*)d_in[8];
    const float* b2   = (const float*)d_in[9];
    const float* W3   = (const float*)d_in[10];
    const float* b3   = (const float*)d_in[11];
    const float* adj_vals = (const float*)d_in[16];
    const int* uids = (const int*)d_in[17];
    const int* pos  = (const int*)d_in[19];
    const int* neg  = (const int*)d_in[20];
    const int* ge   = (const int*)d_in[21];
    const int* de   = (const int*)d_in[22];
    const int* arows = (const int*)d_in[23];
    const int* acols = (const int*)d_in[24];
    const unsigned* drop1 = (const unsigned*)d_in[25];
    const unsigned* drop2 = (const unsigned*)d_in[26];
    float* out = (float*)d_out;

    float *hg,*hd,*Eg0b,*Ed0b,*Eg,*Ed;
    float *alg,*arg,*ald,*ard,*w1,*w2,*h2,*sv,*pw1,*pw2;
    int *ctl,*offs,*payg,*payd,*pc1,*pc2;
    __nv_bfloat16 *Eg0h,*Ed0h,*attWt,*W1t,*W2t,*catb,*h1b;
    double *lr,*reg;
    cudaGetSymbolAddress((void**)&hg,   d_hg);
    cudaGetSymbolAddress((void**)&hd,   d_hd);
    cudaGetSymbolAddress((void**)&Eg0b, d_Eg0b);
    cudaGetSymbolAddress((void**)&Ed0b, d_Ed0b);
    cudaGetSymbolAddress((void**)&Eg,   d_Eg);
    cudaGetSymbolAddress((void**)&Ed,   d_Ed);
    cudaGetSymbolAddress((void**)&alg,  d_alg);
    cudaGetSymbolAddress((void**)&arg,  d_arg_);
    cudaGetSymbolAddress((void**)&ald,  d_ald);
    cudaGetSymbolAddress((void**)&ard,  d_ard);
    cudaGetSymbolAddress((void**)&w1,   d_w1);
    cudaGetSymbolAddress((void**)&w2,   d_w2);
    cudaGetSymbolAddress((void**)&h2,   d_h2);
    cudaGetSymbolAddress((void**)&sv,   d_s);
    cudaGetSymbolAddress((void**)&ctl,  d_ctl);
    cudaGetSymbolAddress((void**)&offs, d_off);
    cudaGetSymbolAddress((void**)&payg, d_payg);
    cudaGetSymbolAddress((void**)&payd, d_payd);
    cudaGetSymbolAddress((void**)&pc1,  d_pc1);
    cudaGetSymbolAddress((void**)&pc2,  d_pc2);
    cudaGetSymbolAddress((void**)&pw1,  d_pw1);
    cudaGetSymbolAddress((void**)&pw2,  d_pw2);
    cudaGetSymbolAddress((void**)&Eg0h, d_Eg0h);
    cudaGetSymbolAddress((void**)&Ed0h, d_Ed0h);
    cudaGetSymbolAddress((void**)&attWt,d_attWt);
    cudaGetSymbolAddress((void**)&W1t,  d_W1t);
    cudaGetSymbolAddress((void**)&W2t,  d_W2t);
    cudaGetSymbolAddress((void**)&catb, d_catb);
    cudaGetSymbolAddress((void**)&h1b,  d_h1b);
    cudaGetSymbolAddress((void**)&lr,   d_lr_acc);
    cudaGetSymbolAddress((void**)&reg,  d_reg_acc);

    const int NP1 = NN + 1;
    int* cnt0 = ctl;            int* cnt1 = ctl + NP1;
    int* cnt2 = ctl + 2*NP1;    int* cnt3 = ctl + 3*NP1;
    int* cur0 = ctl + 4*NP1;    int* cur1 = ctl + 5*NP1;
    int* cur2 = ctl + 6*NP1;    int* cur3 = ctl + 7*NP1;
    int* off0 = offs;           int* off1 = offs + NP1;
    int* off2 = offs + 2*NP1;   int* off3 = offs + 3*NP1;

    // zero control block + scalar accumulators
    cudaMemsetAsync(ctl, 0, sizeof(int)*8*NP1);
    cudaMemsetAsync(lr,  0, sizeof(double));
    cudaMemsetAsync(reg, 0, sizeof(double));

    // edge weights + bf16 conversions
    wprep_k<<<(NNZ_+255)/256, 256>>>(adj_vals, drop1, drop2, w1, w2, NNZ_);
    conv2_k<<<(2*NN*DIM/4+255)/256, 256>>>(Eg0, Ed0, Eg0h, Ed0h, NN*DIM/4);
    convT_k<<<(DIM*DIM+255)/256, 256>>>(attW, attWt, DIM, DIM);
    convT_k<<<(2*DIM*DIM+255)/256, 256>>>(W1, W1t, 2*DIM, DIM);
    convT_k<<<(DIM*DIM+255)/256, 256>>>(W2, W2t, DIM, DIM);

    // CSR builds: gene by tgt, drug by tgt, adj by rows, adj by cols
    hist_k<<<(NE_+255)/256, 256>>>(ge+NE_, cnt0, NE_);
    hist_k<<<(NE_+255)/256, 256>>>(de+NE_, cnt1, NE_);
    hist_k<<<(NNZ_+255)/256, 256>>>(arows, cnt2, NNZ_);
    hist_k<<<(NNZ_+255)/256, 256>>>(acols, cnt3, NNZ_);
    ScanArgs sa;
    sa.cnt[0]=cnt0; sa.cnt[1]=cnt1; sa.cnt[2]=cnt2; sa.cnt[3]=cnt3;
    sa.off[0]=off0; sa.off[1]=off1; sa.off[2]=off2; sa.off[3]=off3;
    scan4_k<<<4, 256>>>(sa, NN);
    build_att_k<<<(NE_+255)/256, 256>>>(ge, ge+NE_, cur0, off0, payg, NE_);
    build_att_k<<<(NE_+255)/256, 256>>>(de, de+NE_, cur1, off1, payd, NE_);
    build_adj_k<<<(NNZ_+255)/256, 256>>>(arows, acols, w1, cur2, off2, pc1, pw1, NNZ_);
    build_adj_k<<<(NNZ_+255)/256, 256>>>(acols, arows, w2, cur3, off3, pc2, pw2, NNZ_);

    // h = X @ att_W for both node sets (tensor cores, z-batched)
    hgemm_k<<<dim3(DIM/128, NNP/128, 2), 256>>>(NNP, DIM, DIM,
        Eg0h, Ed0h, attWt, hg, hd, nullptr, nullptr, nullptr, 0);

    // attention logits components (both graphs)
    rowdot2_k<<<dim3((NN*32+255)/256, 1, 2), 256>>>(hg, hd, atta, alg, arg, ald, ard, NN);

    // fused attention softmax + aggregate + combine (gather, no atomics)
    att_csr_k<<<(NN*32+255)/256, 256>>>(off0, payg, alg, arg, hg, Eg0, Eg0b, NN);
    att_csr_k<<<(NN*32+255)/256, 256>>>(off1, payd, ald, ard, hd, Ed0, Ed0b, NN);

    // CSR SpMM (gather, no atomics, no memset)
    spmm_csr_k<<<(NN*32+255)/256, 256>>>(off2, pc1, pw1, Ed0b, Eg, NN);
    spmm_csr_k<<<(NN*32+255)/256, 256>>>(off3, pc2, pw2, Eg0b, Ed, NN);

    // gather MLP inputs into one [2B, 512] bf16 matrix (pos then neg)
    gatherb_k<<<(2*B_*128)/256, 256>>>(Eg, Ed, uids, pos, neg, catb);

    // MLP on concatenated batch (tensor cores)
    hgemm_k<<<dim3(DIM/128, (2*B_)/128, 1), 256>>>(2*B_, DIM, 2*DIM,
        catb, catb, W1t, nullptr, nullptr, h1b, h1b, b1, 1);
    hgemm_k<<<dim3(DIM/128, (2*B_)/128, 1), 256>>>(2*B_, DIM, DIM,
        h1b, h1b, W2t, h2, h2, nullptr, nullptr, b2, 1);
    score_k<<<(2*B_*32)/256, 256>>>(h2, W3, b3, sv, 2*B_);

    // losses
    loss_k<<<64, 256>>>(sv, B_, lr);
    P16 pp;
    for (int i = 0; i < 16; i++){ pp.p[i] = (const float*)d_in[i]; pp.n[i] = in_sizes[i]; }
    sumsq16_k<<<dim3(160, 16), 256>>>(pp, reg);
    final_k<<<1, 1>>>(lr, reg, out, B_);
}

// round 9
// speedup vs baseline: 4.1465x; 1.1901x over previous
#include <cuda_runtime.h>
#include <cuda_bf16.h>
#include <math.h>

#define NN    20000     // N_U == N_I
#define NNP   20096     // padded to multiple of 128
#define DIM   256
#define NNZ_  600000
#define NE_   300000
#define B_    8192

// ---------------- persistent device scratch (no allocations allowed) -------
__device__ float d_h2[2*B_*DIM];
__device__ float d_alg[NN], d_arg_[NN], d_ald[NN], d_ard[NN];
__device__ float d_w1[NNZ_], d_w2[NNZ_];
__device__ float d_s[2*B_];
__device__ double d_lr_acc, d_reg_acc;
// CSR structures (rebuilt every launch)
__device__ int   d_ctl[8*(NN+1)];            // 4 counters + 4 cursors
__device__ int   d_off[4*(NN+1)];            // 4 offset arrays
__device__ int   d_payg[NE_], d_payd[NE_];   // attention payload: src node
__device__ int   d_pc1[NNZ_], d_pc2[NNZ_];   // spmm payload: col
__device__ float d_pw1[NNZ_], d_pw2[NNZ_];   // spmm payload: weight
// bf16 scratch
__device__ __nv_bfloat16 d_Eg0h[NNP*DIM], d_Ed0h[NNP*DIM];   // padded rows stay 0
__device__ __nv_bfloat16 d_hgb[NNP*DIM], d_hdb[NNP*DIM];     // h = X @ att_W
__device__ __nv_bfloat16 d_Eg0b[NN*DIM], d_Ed0b[NN*DIM];     // post-attention emb
__device__ __nv_bfloat16 d_Egb[NN*DIM], d_Edb[NN*DIM];       // post-spmm emb
__device__ __nv_bfloat16 d_attWt[DIM*DIM];                    // [N,K] transposed
__device__ __nv_bfloat16 d_W1t[DIM*2*DIM], d_W2t[DIM*DIM];    // transposed
__device__ __nv_bfloat16 d_catb[2*B_*2*DIM], d_h1b[2*B_*DIM];

struct ScanArgs { const int* cnt[4]; int* off[4]; };
struct P16 { const float* p[16]; int n[16]; };

__device__ __forceinline__ double softplusd(double x){
    return fmax(x, 0.0) + log1p(exp(-fabs(x)));
}

__device__ __forceinline__ void unpack8(uint4 v, float* f){
    __nv_bfloat162* p = (__nv_bfloat162*)&v;
    #pragma unroll
    for (int i = 0; i < 4; i++){
        float2 t = __bfloat1622float2(p[i]);
        f[2*i] = t.x; f[2*i+1] = t.y;
    }
}

__device__ __forceinline__ uint4 pack8(const float* f){
    uint4 v;
    __nv_bfloat162* p = (__nv_bfloat162*)&v;
    #pragma unroll
    for (int i = 0; i < 4; i++)
        p[i] = __floats2bfloat162_rn(f[2*i], f[2*i+1]);
    return v;
}

// ---------------- f32 -> bf16, both embedding tables, vectorized ----------
__global__ void conv2_k(const float* __restrict__ a, const float* __restrict__ b,
                        __nv_bfloat16* __restrict__ oa, __nv_bfloat16* __restrict__ ob,
                        int nvec){
    int i = blockIdx.x*blockDim.x + threadIdx.x;
    if (i >= 2*nvec) return;
    const float* src; __nv_bfloat16* dst; int j;
    if (i < nvec){ src = a; dst = oa; j = i; }
    else         { src = b; dst = ob; j = i - nvec; }
    float4 v = ((const float4*)src)[j];
    __nv_bfloat162 lo = __floats2bfloat162_rn(v.x, v.y);
    __nv_bfloat162 hi = __floats2bfloat162_rn(v.z, v.w);
    uint2 pk; pk.x = *(unsigned*)&lo; pk.y = *(unsigned*)&hi;
    ((uint2*)dst)[j] = pk;
}

// ---------------- f32 [K,N] -> bf16 [N,K] transpose ------------------------
__global__ void convT_k(const float* __restrict__ in, __nv_bfloat16* __restrict__ out,
                        int K, int N){
    int i = blockIdx.x*blockDim.x + threadIdx.x;
    if (i >= K*N) return;
    int k = i / N, n = i % N;
    out[(size_t)n*K + k] = __float2bfloat16(in[i]);
}

// ---------------- dropout-scaled edge weights ------------------------------
__global__ void wprep_k(const float* __restrict__ vals, const unsigned* __restrict__ m1,
                        const unsigned* __restrict__ m2,
                        float* __restrict__ w1, float* __restrict__ w2, int E){
    int i = blockIdx.x*blockDim.x + threadIdx.x;
    if (i >= E) return;
    float v = vals[i] * (1.0f/0.9f);
    w1[i] = m1[i] ? v : 0.f;
    w2[i] = m2[i] ? v : 0.f;
}

// ---------------- CSR build: histogram / scan / scatter --------------------
__global__ void hist_k(const int* __restrict__ keys, int* __restrict__ cnt, int E){
    int i = blockIdx.x*blockDim.x + threadIdx.x;
    if (i < E) atomicAdd(&cnt[keys[i]], 1);
}

// one block per array; 256 threads; exclusive scan of n counts -> off[0..n]
__global__ void scan4_k(ScanArgs a, int n){
    const int* cnt = a.cnt[blockIdx.x];
    int* off = a.off[blockIdx.x];
    __shared__ int part[256];
    int tid = threadIdx.x;
    int per = (n + 255) / 256;
    int st = tid*per, en = st + per; if (en > n) en = n;
    int s = 0;
    for (int i = st; i < en; i++) s += cnt[i];
    part[tid] = s;
    __syncthreads();
    for (int o = 1; o < 256; o <<= 1){
        int v = (tid >= o) ? part[tid - o] : 0;
        __syncthreads();
        part[tid] += v;
        __syncthreads();
    }
    int base = tid ? part[tid - 1] : 0;
    for (int i = st; i < en; i++){ off[i] = base; base += cnt[i]; }
    if (tid == 255) off[n] = part[255];
}

__global__ void build_att_k(const int* __restrict__ src, const int* __restrict__ tgt,
                            int* __restrict__ cursor, const int* __restrict__ off,
                            int* __restrict__ pay, int E){
    int i = blockIdx.x*blockDim.x + threadIdx.x;
    if (i >= E) return;
    int t = tgt[i];
    int p = atomicAdd(&cursor[t], 1);
    pay[off[t] + p] = src[i];
}

__global__ void build_adj_k(const int* __restrict__ keys, const int* __restrict__ other,
                            const float* __restrict__ w,
                            int* __restrict__ cursor, const int* __restrict__ off,
                            int* __restrict__ pcol, float* __restrict__ pw, int E){
    int i = blockIdx.x*blockDim.x + threadIdx.x;
    if (i >= E) return;
    int k = keys[i];
    int p = atomicAdd(&cursor[k], 1);
    int slot = off[k] + p;
    pcol[slot] = other[i];
    pw[slot]   = w[i];
}

// ---------------- bf16 tensor-core GEMM ------------------------------------
// C[M,N] = A[M,K] @ B[K,N]; A bf16 row-major, Bt = B^T bf16 [N,K].
// M % 128 == 0, N % 128 == 0, K % 32 == 0 (padded; no guards).
__global__ void hgemm_k(int M, int N, int K,
    const __nv_bfloat16* __restrict__ A0, const __nv_bfloat16* __restrict__ A1,
    const __nv_bfloat16* __restrict__ Bt,
    float* __restrict__ Cf0, float* __restrict__ Cf1,
    __nv_bfloat16* __restrict__ Cb0, __nv_bfloat16* __restrict__ Cb1,
    const float* __restrict__ bias, int relu){
    const __nv_bfloat16* A = blockIdx.z ? A1 : A0;
    float* Cf = blockIdx.z ? Cf1 : Cf0;
    __nv_bfloat16* Cb = blockIdx.z ? Cb1 : Cb0;
    __shared__ __nv_bfloat16 As[128][40];
    __shared__ __nv_bfloat16 Bs[128][40];
    int tid = threadIdx.x;
    int wid = tid >> 5, lane = tid & 31;
    int g = lane >> 2, tg = lane & 3;
    int wm = (wid & 1) * 64, wn = (wid >> 1) * 32;
    int row0 = blockIdx.y * 128, col0 = blockIdx.x * 128;
    float acc[4][4][4] = {};
    for (int k0 = 0; k0 < K; k0 += 32){
        #pragma unroll
        for (int i = 0; i < 2; i++){
            int idx = tid + i*256;
            int r = idx >> 2, c = (idx & 3) * 8;
            *(uint4*)&As[r][c] = *(const uint4*)(A  + (size_t)(row0 + r)*K + k0 + c);
            *(uint4*)&Bs[r][c] = *(const uint4*)(Bt + (size_t)(col0 + r)*K + k0 + c);
        }
        __syncthreads();
        #pragma unroll
        for (int ks = 0; ks < 2; ks++){
            unsigned af[4][4], bfr[4][2];
            #pragma unroll
            for (int mt = 0; mt < 4; mt++){
                int rm = wm + mt*16;
                af[mt][0] = *(unsigned*)&As[rm + g    ][ks*16 + tg*2];
                af[mt][1] = *(unsigned*)&As[rm + g + 8][ks*16 + tg*2];
                af[mt][2] = *(unsigned*)&As[rm + g    ][ks*16 + tg*2 + 8];
                af[mt][3] = *(unsigned*)&As[rm + g + 8][ks*16 + tg*2 + 8];
            }
            #pragma unroll
            for (int nt = 0; nt < 4; nt++){
                int rn = wn + nt*8 + g;
                bfr[nt][0] = *(unsigned*)&Bs[rn][ks*16 + tg*2];
                bfr[nt][1] = *(unsigned*)&Bs[rn][ks*16 + tg*2 + 8];
            }
            #pragma unroll
            for (int mt = 0; mt < 4; mt++)
                #pragma unroll
                for (int nt = 0; nt < 4; nt++)
                    asm volatile(
                        "mma.sync.aligned.m16n8k16.row.col.f32.bf16.bf16.f32 "
                        "{%0,%1,%2,%3},{%4,%5,%6,%7},{%8,%9},{%0,%1,%2,%3};"
                        : "+f"(acc[mt][nt][0]), "+f"(acc[mt][nt][1]),
                          "+f"(acc[mt][nt][2]), "+f"(acc[mt][nt][3])
                        : "r"(af[mt][0]), "r"(af[mt][1]), "r"(af[mt][2]), "r"(af[mt][3]),
                          "r"(bfr[nt][0]), "r"(bfr[nt][1]));
        }
        __syncthreads();
    }
    #pragma unroll
    for (int mt = 0; mt < 4; mt++){
        #pragma unroll
        for (int nt = 0; nt < 4; nt++){
            int col = col0 + wn + nt*8 + tg*2;
            float b0v = 0.f, b1v = 0.f;
            if (bias){ b0v = bias[col]; b1v = bias[col+1]; }
            #pragma unroll
            for (int h = 0; h < 2; h++){
                int row = row0 + wm + mt*16 + g + h*8;
                float v0 = acc[mt][nt][h*2+0] + b0v;
                float v1 = acc[mt][nt][h*2+1] + b1v;
                if (relu){ v0 = fmaxf(v0, 0.f); v1 = fmaxf(v1, 0.f); }
                if (Cb){
                    *(__nv_bfloat162*)(Cb + (size_t)row*N + col) =
                        __floats2bfloat162_rn(v0, v1);
                } else {
                    *(float2*)(Cf + (size_t)row*N + col) = make_float2(v0, v1);
                }
            }
        }
    }
}

// ---------------- per-node attention dots (bf16 h), both graphs ------------
__global__ void rowdot2_k(const __nv_bfloat16* __restrict__ hg,
                          const __nv_bfloat16* __restrict__ hd,
                          const float* __restrict__ a,
                          float* __restrict__ alg, float* __restrict__ arg,
                          float* __restrict__ ald, float* __restrict__ ard, int n){
    const __nv_bfloat16* h = blockIdx.z ? hd : hg;
    float* al = blockIdx.z ? ald : alg;
    float* ar = blockIdx.z ? ard : arg;
    int w = (blockIdx.x*blockDim.x + threadIdx.x) >> 5;
    int lane = threadIdx.x & 31;
    if (w >= n) return;
    uint4 hv = ((const uint4*)(h + (size_t)w*DIM))[lane];   // 8 bf16
    float f[8]; unpack8(hv, f);
    int j = lane*8;
    float a1 = 0.f, a2 = 0.f;
    #pragma unroll
    for (int q = 0; q < 2; q++){
        float4 av = *(const float4*)(a + j + q*4);
        float4 bv = *(const float4*)(a + DIM + j + q*4);
        a1 += f[q*4]*av.x + f[q*4+1]*av.y + f[q*4+2]*av.z + f[q*4+3]*av.w;
        a2 += f[q*4]*bv.x + f[q*4+1]*bv.y + f[q*4+2]*bv.z + f[q*4+3]*bv.w;
    }
    #pragma unroll
    for (int o = 16; o; o >>= 1){
        a1 += __shfl_xor_sync(0xffffffffu, a1, o);
        a2 += __shfl_xor_sync(0xffffffffu, a2, o);
    }
    if (lane == 0){ al[w] = a1; ar[w] = a2; }
}

// ---------------- fused CSR attention: softmax + aggregate + combine -------
// out[t] = bf16( 0.1 * (sum_e ex_e * h[src_e]) / (sum ex + 1e-9) + base[t] )
__global__ void att_csr_k(const int* __restrict__ off, const int* __restrict__ pay,
                          const float* __restrict__ al, const float* __restrict__ ar,
                          const __nv_bfloat16* __restrict__ h,
                          const float* __restrict__ base,
                          __nv_bfloat16* __restrict__ out, int n){
    int t = (blockIdx.x*blockDim.x + threadIdx.x) >> 5;
    int lane = threadIdx.x & 31;
    if (t >= n) return;
    int s0 = off[t], s1 = off[t+1];
    float art = ar[t];
    float m = -1e30f;
    for (int i = s0 + lane; i < s1; i += 32){
        float x = al[pay[i]] + art;
        x = x > 0.f ? x : 0.2f*x;
        m = fmaxf(m, x);
    }
    #pragma unroll
    for (int o = 16; o; o >>= 1) m = fmaxf(m, __shfl_xor_sync(0xffffffffu, m, o));
    float den = 0.f;
    float acc[8] = {};
    const uint4* hb = (const uint4*)h;
    for (int i = s0; i < s1; i++){
        int s = pay[i];
        float x = al[s] + art;
        x = x > 0.f ? x : 0.2f*x;
        float ex = __expf(x - m);
        den += ex;
        uint4 hv = hb[(size_t)s*32 + lane];
        float f[8]; unpack8(hv, f);
        #pragma unroll
        for (int j = 0; j < 8; j++) acc[j] += ex*f[j];
    }
    float dinv = 0.1f / (den + 1e-9f);
    const float4* bp = (const float4*)base + (size_t)t*64 + lane*2;
    float4 b0 = bp[0], b1 = bp[1];
    float o[8];
    o[0]=acc[0]*dinv+b0.x; o[1]=acc[1]*dinv+b0.y; o[2]=acc[2]*dinv+b0.z; o[3]=acc[3]*dinv+b0.w;
    o[4]=acc[4]*dinv+b1.x; o[5]=acc[5]*dinv+b1.y; o[6]=acc[6]*dinv+b1.z; o[7]=acc[7]*dinv+b1.w;
    ((uint4*)out)[(size_t)t*32 + lane] = pack8(o);
}

// ---------------- CSR SpMM: dst[r] = bf16( sum_e w_e * src[col_e] ) --------
__global__ void spmm_csr_k(const int* __restrict__ off, const int* __restrict__ pcol,
                           const float* __restrict__ pw,
                           const __nv_bfloat16* __restrict__ src,
                           __nv_bfloat16* __restrict__ dst, int n){
    int r = (blockIdx.x*blockDim.x + threadIdx.x) >> 5;
    int lane = threadIdx.x & 31;
    if (r >= n) return;
    int s0 = off[r], s1 = off[r+1];
    float acc[8] = {};
    const uint4* sb = (const uint4*)src;
    for (int i = s0; i < s1; i++){
        float v = pw[i];
        if (v == 0.f) continue;
        int c = pcol[i];
        uint4 sv = sb[(size_t)c*32 + lane];
        float f[8]; unpack8(sv, f);
        #pragma unroll
        for (int j = 0; j < 8; j++) acc[j] += v*f[j];
    }
    ((uint4*)dst)[(size_t)r*32 + lane] = pack8(acc);
}

// ---------------- gather [u, item] bf16 rows into [2B, 512] bf16 -----------
__global__ void gatherb_k(const __nv_bfloat16* __restrict__ Eg,
                          const __nv_bfloat16* __restrict__ Ed,
                          const int* __restrict__ uids, const int* __restrict__ pos,
                          const int* __restrict__ neg, __nv_bfloat16* __restrict__ out){
    int gi = blockIdx.x*blockDim.x + threadIdx.x;
    if (gi >= 2*B_*64) return;
    int b = gi >> 6;
    int q = gi & 63;          // uint4 index within 512-col row
    int ub = (b < B_) ? b : b - B_;
    uint4 v;
    if (q < 32) v = ((const uint4*)Eg)[(size_t)uids[ub]*32 + q];
    else {
        int it = (b < B_) ? pos[ub] : neg[ub];
        v = ((const uint4*)Ed)[(size_t)it*32 + q - 32];
    }
    ((uint4*)out)[(size_t)b*64 + q] = v;
}

// ---------------- final linear layer: s = h2 @ W3 + b3 ---------------------
__global__ void score_k(const float* __restrict__ h2, const float* __restrict__ W3,
                        const float* __restrict__ b3, float* __restrict__ s, int R){
    int w = (blockIdx.x*blockDim.x + threadIdx.x) >> 5;
    int lane = threadIdx.x & 31;
    if (w >= R) return;
    const float* hr = h2 + (size_t)w*DIM;
    float acc = 0.f;
    for (int k = lane*4; k < DIM; k += 128){
        float4 hv = *(const float4*)(hr + k);
        float4 wv = *(const float4*)(W3 + k);
        acc += hv.x*wv.x + hv.y*wv.y + hv.z*wv.z + hv.w*wv.w;
    }
    #pragma unroll
    for (int o = 16; o; o >>= 1) acc += __shfl_xor_sync(0xffffffffu, acc, o);
    if (lane == 0) s[w] = acc + b3[0];
}

// ---------------- loss_r reduction -----------------------------------------
__global__ void loss_k(const float* __restrict__ s, int B, double* acc){
    __shared__ double sh[256];
    double local = 0.0;
    for (int i = blockIdx.x*blockDim.x + threadIdx.x; i < B; i += gridDim.x*blockDim.x){
        double ps = s[i], ns = s[B + i];
        local += softplusd(-ps) + softplusd(ns) + softplusd(ns - ps);
    }
    sh[threadIdx.x] = local;
    __syncthreads();
    for (int st = 128; st; st >>= 1){
        if (threadIdx.x < st) sh[threadIdx.x] += sh[threadIdx.x + st];
        __syncthreads();
    }
    if (threadIdx.x == 0) atomicAdd(acc, sh[0]);
}

// ---------------- sum of squares over all 16 params, one launch ------------
__global__ void sumsq16_k(P16 a, double* acc){
    const float* p = a.p[blockIdx.y];
    int n = a.n[blockIdx.y];
    __shared__ double sh[256];
    double local = 0.0;
    for (int i = blockIdx.x*blockDim.x + threadIdx.x; i < n; i += gridDim.x*blockDim.x){
        double v = p[i];
        local += v*v;
    }
    sh[threadIdx.x] = local;
    __syncthreads();
    for (int st = 128; st; st >>= 1){
        if (threadIdx.x < st) sh[threadIdx.x] += sh[threadIdx.x + st];
        __syncthreads();
    }
    if (threadIdx.x == 0 && sh[0] != 0.0) atomicAdd(acc, sh[0]);
}

// ---------------- final combine --------------------------------------------
__global__ void final_k(const double* lr, const double* reg, float* out, int B){
    double l_r = (*lr) / (double)B;
    out[0] = (float)(1e-7 * (*reg) + l_r);
    out[1] = (float)l_r;
    out[2] = 0.f;
}

// ---------------- launch ----------------------------------------------------
extern "C" void kernel_launch(void* const* d_in, const int* in_sizes, int n_in,
                              void* d_out, int out_size){
    const float* Eg0  = (const float*)d_in[0];
    const float* Ed0  = (const float*)d_in[1];
    const float* attW = (const float*)d_in[2];
    const float* atta = (const float*)d_in[3];
    const float* W1   = (const float*)d_in[6];
    const float* b1   = (const float*)d_in[7];
    const float* W2   = (const float*)d_in[8];
    const float* b2   = (const float*)d_in[9];
    const float* W3   = (const float*)d_in[10];
    const float* b3   = (const float*)d_in[11];
    const float* adj_vals = (const float*)d_in[16];
    const int* uids = (const int*)d_in[17];
    const int* pos  = (const int*)d_in[19];
    const int* neg  = (const int*)d_in[20];
    const int* ge   = (const int*)d_in[21];
    const int* de   = (const int*)d_in[22];
    const int* arows = (const int*)d_in[23];
    const int* acols = (const int*)d_in[24];
    const unsigned* drop1 = (const unsigned*)d_in[25];
    const unsigned* drop2 = (const unsigned*)d_in[26];
    float* out = (float*)d_out;

    float *alg,*arg,*ald,*ard,*w1,*w2,*h2,*sv,*pw1,*pw2;
    int *ctl,*offs,*payg,*payd,*pc1,*pc2;
    __nv_bfloat16 *Eg0h,*Ed0h,*hgb,*hdb,*Eg0b,*Ed0b,*Egb,*Edb;
    __nv_bfloat16 *attWt,*W1t,*W2t,*catb,*h1b;
    double *lr,*reg;
    cudaGetSymbolAddress((void**)&alg,  d_alg);
    cudaGetSymbolAddress((void**)&arg,  d_arg_);
    cudaGetSymbolAddress((void**)&ald,  d_ald);
    cudaGetSymbolAddress((void**)&ard,  d_ard);
    cudaGetSymbolAddress((void**)&w1,   d_w1);
    cudaGetSymbolAddress((void**)&w2,   d_w2);
    cudaGetSymbolAddress((void**)&h2,   d_h2);
    cudaGetSymbolAddress((void**)&sv,   d_s);
    cudaGetSymbolAddress((void**)&ctl,  d_ctl);
    cudaGetSymbolAddress((void**)&offs, d_off);
    cudaGetSymbolAddress((void**)&payg, d_payg);
    cudaGetSymbolAddress((void**)&payd, d_payd);
    cudaGetSymbolAddress((void**)&pc1,  d_pc1);
    cudaGetSymbolAddress((void**)&pc2,  d_pc2);
    cudaGetSymbolAddress((void**)&pw1,  d_pw1);
    cudaGetSymbolAddress((void**)&pw2,  d_pw2);
    cudaGetSymbolAddress((void**)&Eg0h, d_Eg0h);
    cudaGetSymbolAddress((void**)&Ed0h, d_Ed0h);
    cudaGetSymbolAddress((void**)&hgb,  d_hgb);
    cudaGetSymbolAddress((void**)&hdb,  d_hdb);
    cudaGetSymbolAddress((void**)&Eg0b, d_Eg0b);
    cudaGetSymbolAddress((void**)&Ed0b, d_Ed0b);
    cudaGetSymbolAddress((void**)&Egb,  d_Egb);
    cudaGetSymbolAddress((void**)&Edb,  d_Edb);
    cudaGetSymbolAddress((void**)&attWt,d_attWt);
    cudaGetSymbolAddress((void**)&W1t,  d_W1t);
    cudaGetSymbolAddress((void**)&W2t,  d_W2t);
    cudaGetSymbolAddress((void**)&catb, d_catb);
    cudaGetSymbolAddress((void**)&h1b,  d_h1b);
    cudaGetSymbolAddress((void**)&lr,   d_lr_acc);
    cudaGetSymbolAddress((void**)&reg,  d_reg_acc);

    const int NP1 = NN + 1;
    int* cnt0 = ctl;            int* cnt1 = ctl + NP1;
    int* cnt2 = ctl + 2*NP1;    int* cnt3 = ctl + 3*NP1;
    int* cur0 = ctl + 4*NP1;    int* cur1 = ctl + 5*NP1;
    int* cur2 = ctl + 6*NP1;    int* cur3 = ctl + 7*NP1;
    int* off0 = offs;           int* off1 = offs + NP1;
    int* off2 = offs + 2*NP1;   int* off3 = offs + 3*NP1;

    // fork-join streams (host-side objects only; cost is capture-time only)
    cudaStream_t sB, sC, sD;
    cudaStreamCreateWithFlags(&sB, cudaStreamNonBlocking);
    cudaStreamCreateWithFlags(&sC, cudaStreamNonBlocking);
    cudaStreamCreateWithFlags(&sD, cudaStreamNonBlocking);
    cudaEvent_t evRoot, evB, evC, evF, evG, evH, evI;
    cudaEventCreateWithFlags(&evRoot, cudaEventDisableTiming);
    cudaEventCreateWithFlags(&evB,    cudaEventDisableTiming);
    cudaEventCreateWithFlags(&evC,    cudaEventDisableTiming);
    cudaEventCreateWithFlags(&evF,    cudaEventDisableTiming);
    cudaEventCreateWithFlags(&evG,    cudaEventDisableTiming);
    cudaEventCreateWithFlags(&evH,    cudaEventDisableTiming);
    cudaEventCreateWithFlags(&evI,    cudaEventDisableTiming);

    cudaEventRecord(evRoot, 0);
    cudaStreamWaitEvent(sB, evRoot, 0);
    cudaStreamWaitEvent(sC, evRoot, 0);

    // ---- stream B: CSR build chain ----
    cudaMemsetAsync(ctl, 0, sizeof(int)*8*NP1, sB);
    wprep_k<<<(NNZ_+255)/256, 256, 0, sB>>>(adj_vals, drop1, drop2, w1, w2, NNZ_);
    hist_k<<<(NE_+255)/256, 256, 0, sB>>>(ge+NE_, cnt0, NE_);
    hist_k<<<(NE_+255)/256, 256, 0, sB>>>(de+NE_, cnt1, NE_);
    hist_k<<<(NNZ_+255)/256, 256, 0, sB>>>(arows, cnt2, NNZ_);
    hist_k<<<(NNZ_+255)/256, 256, 0, sB>>>(acols, cnt3, NNZ_);
    ScanArgs sa;
    sa.cnt[0]=cnt0; sa.cnt[1]=cnt1; sa.cnt[2]=cnt2; sa.cnt[3]=cnt3;
    sa.off[0]=off0; sa.off[1]=off1; sa.off[2]=off2; sa.off[3]=off3;
    scan4_k<<<4, 256, 0, sB>>>(sa, NN);
    build_att_k<<<(NE_+255)/256, 256, 0, sB>>>(ge, ge+NE_, cur0, off0, payg, NE_);
    build_att_k<<<(NE_+255)/256, 256, 0, sB>>>(de, de+NE_, cur1, off1, payd, NE_);
    build_adj_k<<<(NNZ_+255)/256, 256, 0, sB>>>(arows, acols, w1, cur2, off2, pc1, pw1, NNZ_);
    build_adj_k<<<(NNZ_+255)/256, 256, 0, sB>>>(acols, arows, w2, cur3, off3, pc2, pw2, NNZ_);
    cudaEventRecord(evB, sB);

    // ---- stream C: scalar zeroing + MLP weight transposes + regularizer ----
    cudaMemsetAsync(lr,  0, sizeof(double), sC);
    cudaMemsetAsync(reg, 0, sizeof(double), sC);
    convT_k<<<(2*DIM*DIM+255)/256, 256, 0, sC>>>(W1, W1t, 2*DIM, DIM);
    convT_k<<<(DIM*DIM+255)/256, 256, 0, sC>>>(W2, W2t, DIM, DIM);
    P16 pp;
    for (int i = 0; i < 16; i++){ pp.p[i] = (const float*)d_in[i]; pp.n[i] = in_sizes[i]; }
    sumsq16_k<<<dim3(48, 16), 256, 0, sC>>>(pp, reg);
    cudaEventRecord(evC, sC);

    // ---- main stream: conversions -> GEMM -> rowdot ----
    conv2_k<<<(2*NN*DIM/4+255)/256, 256>>>(Eg0, Ed0, Eg0h, Ed0h, NN*DIM/4);
    convT_k<<<(DIM*DIM+255)/256, 256>>>(attW, attWt, DIM, DIM);
    hgemm_k<<<dim3(DIM/128, NNP/128, 2), 256>>>(NNP, DIM, DIM,
        Eg0h, Ed0h, attWt, nullptr, nullptr, hgb, hdb, nullptr, 0);
    rowdot2_k<<<dim3((NN*32+255)/256, 1, 2), 256>>>(hgb, hdb, atta, alg, arg, ald, ard, NN);

    // join CSR, fork gene/drug attention
    cudaStreamWaitEvent(0, evB, 0);
    cudaEventRecord(evF, 0);
    cudaStreamWaitEvent(sD, evF, 0);
    att_csr_k<<<(NN*32+255)/256, 256>>>(off0, payg, alg, arg, hgb, Eg0, Eg0b, NN);
    cudaEventRecord(evG, 0);
    att_csr_k<<<(NN*32+255)/256, 256, 0, sD>>>(off1, payd, ald, ard, hdb, Ed0, Ed0b, NN);
    cudaEventRecord(evH, sD);

    // cross dependencies: Eg = adj@Ed0b on main, Ed = adjT@Eg0b on sD
    cudaStreamWaitEvent(0, evH, 0);
    spmm_csr_k<<<(NN*32+255)/256, 256>>>(off2, pc1, pw1, Ed0b, Egb, NN);
    cudaStreamWaitEvent(sD, evG, 0);
    spmm_csr_k<<<(NN*32+255)/256, 256, 0, sD>>>(off3, pc2, pw2, Eg0b, Edb, NN);
    cudaEventRecord(evI, sD);
    cudaStreamWaitEvent(0, evI, 0);

    // gather MLP inputs (pure bf16 copy)
    gatherb_k<<<(2*B_*64+255)/256, 256>>>(Egb, Edb, uids, pos, neg, catb);

    // MLP on concatenated batch (tensor cores); needs W1t/W2t from sC
    cudaStreamWaitEvent(0, evC, 0);
    hgemm_k<<<dim3(DIM/128, (2*B_)/128, 1), 256>>>(2*B_, DIM, 2*DIM,
        catb, catb, W1t, nullptr, nullptr, h1b, h1b, b1, 1);
    hgemm_k<<<dim3(DIM/128, (2*B_)/128, 1), 256>>>(2*B_, DIM, DIM,
        h1b, h1b, W2t, h2, h2, nullptr, nullptr, b2, 1);
    score_k<<<(2*B_*32)/256, 256>>>(h2, W3, b3, sv, 2*B_);
    loss_k<<<64, 256>>>(sv, B_, lr);
    final_k<<<1, 1>>>(lr, reg, out, B_);

    cudaEventDestroy(evRoot); cudaEventDestroy(evB); cudaEventDestroy(evC);
    cudaEventDestroy(evF); cudaEventDestroy(evG); cudaEventDestroy(evH);
    cudaEventDestroy(evI);
    cudaStreamDestroy(sB); cudaStreamDestroy(sC); cudaStreamDestroy(sD);
}

// round 10
// speedup vs baseline: 6.0832x; 1.4671x over previous
#include <cuda_runtime.h>
#include <cuda_bf16.h>
#include <math.h>

#define NN    20000     // N_U == N_I
#define NNP   20096     // padded to multiple of 128
#define DIM   256
#define NNZ_  600000
#define NE_   300000
#define B_    8192

// ---------------- persistent device scratch (no allocations allowed) -------
__device__ float d_alg[NN], d_arg_[NN], d_ald[NN], d_ard[NN];
__device__ float d_s[2*B_];
__device__ double d_lr_acc, d_reg_acc;
// CSR structures (rebuilt every launch)
__device__ int   d_ctl[8*(NN+1)];            // 4 counters + 4 cursors
__device__ int   d_off[4*(NN+1)];            // 4 offset arrays
__device__ int   d_payg[NE_], d_payd[NE_];   // attention payload: src node
__device__ int   d_pc1[NNZ_], d_pc2[NNZ_];   // spmm payload: col
__device__ float d_pw1[NNZ_], d_pw2[NNZ_];   // spmm payload: weight
// bf16 scratch
__device__ __nv_bfloat16 d_Eg0h[NNP*DIM], d_Ed0h[NNP*DIM];   // padded rows stay 0
__device__ __nv_bfloat16 d_hgb[NNP*DIM], d_hdb[NNP*DIM];     // h = X @ att_W
__device__ __nv_bfloat16 d_Eg0b[NN*DIM], d_Ed0b[NN*DIM];     // post-attention emb
__device__ __nv_bfloat16 d_attWt[DIM*DIM];                    // [N,K] transposed
__device__ __nv_bfloat16 d_W1t[DIM*2*DIM], d_W2t[DIM*DIM];    // transposed
__device__ __nv_bfloat16 d_catb[2*B_*2*DIM], d_h1b[2*B_*DIM];

struct ScanArgs { const int* cnt[4]; int* off[4]; };
struct P16 { const float* p[16]; int n[16]; };

__device__ __forceinline__ double softplusd(double x){
    return fmax(x, 0.0) + log1p(exp(-fabs(x)));
}

__device__ __forceinline__ void unpack8(uint4 v, float* f){
    __nv_bfloat162* p = (__nv_bfloat162*)&v;
    #pragma unroll
    for (int i = 0; i < 4; i++){
        float2 t = __bfloat1622float2(p[i]);
        f[2*i] = t.x; f[2*i+1] = t.y;
    }
}

__device__ __forceinline__ uint4 pack8(const float* f){
    uint4 v;
    __nv_bfloat162* p = (__nv_bfloat162*)&v;
    #pragma unroll
    for (int i = 0; i < 4; i++)
        p[i] = __floats2bfloat162_rn(f[2*i], f[2*i+1]);
    return v;
}

__device__ __forceinline__ float bfr(float x){
    return __bfloat162float(__float2bfloat16(x));
}

// ---------------- f32 -> bf16, both embedding tables, vectorized ----------
__global__ void conv2_k(const float* __restrict__ a, const float* __restrict__ b,
                        __nv_bfloat16* __restrict__ oa, __nv_bfloat16* __restrict__ ob,
                        int nvec){
    int i = blockIdx.x*blockDim.x + threadIdx.x;
    if (i >= 2*nvec) return;
    const float* src; __nv_bfloat16* dst; int j;
    if (i < nvec){ src = a; dst = oa; j = i; }
    else         { src = b; dst = ob; j = i - nvec; }
    float4 v = ((const float4*)src)[j];
    __nv_bfloat162 lo = __floats2bfloat162_rn(v.x, v.y);
    __nv_bfloat162 hi = __floats2bfloat162_rn(v.z, v.w);
    uint2 pk; pk.x = *(unsigned*)&lo; pk.y = *(unsigned*)&hi;
    ((uint2*)dst)[j] = pk;
}

// ---------------- all three weight transposes, one launch ------------------
__global__ void convT3_k(const float* __restrict__ attW, const float* __restrict__ W1,
                         const float* __restrict__ W2,
                         __nv_bfloat16* __restrict__ attWt, __nv_bfloat16* __restrict__ W1t,
                         __nv_bfloat16* __restrict__ W2t){
    int z = blockIdx.z;
    const float* in; __nv_bfloat16* out; int K, N;
    if (z == 0){ in = attW; out = attWt; K = DIM;   N = DIM; }
    else if (z == 1){ in = W1; out = W1t; K = 2*DIM; N = DIM; }
    else { in = W2; out = W2t; K = DIM; N = DIM; }
    int i = blockIdx.x*blockDim.x + threadIdx.x;
    if (i >= K*N) return;
    int k = i / N, n = i % N;
    out[(size_t)n*K + k] = __float2bfloat16(in[i]);
}

// ---------------- all four histograms, one launch --------------------------
__global__ void hist4_k(const int* __restrict__ k0, const int* __restrict__ k1,
                        const int* __restrict__ k2, const int* __restrict__ k3,
                        int* __restrict__ c0, int* __restrict__ c1,
                        int* __restrict__ c2, int* __restrict__ c3){
    int i = blockIdx.x*blockDim.x + threadIdx.x;
    if (i < NE_)                  atomicAdd(&c0[k0[i]], 1);
    else if (i < 2*NE_)           atomicAdd(&c1[k1[i - NE_]], 1);
    else if (i < 2*NE_ + NNZ_)    atomicAdd(&c2[k2[i - 2*NE_]], 1);
    else if (i < 2*NE_ + 2*NNZ_)  atomicAdd(&c3[k3[i - 2*NE_ - NNZ_]], 1);
}

// one block per array; 256 threads; exclusive scan of n counts -> off[0..n]
__global__ void scan4_k(ScanArgs a, int n){
    const int* cnt = a.cnt[blockIdx.x];
    int* off = a.off[blockIdx.x];
    __shared__ int part[256];
    int tid = threadIdx.x;
    int per = (n + 255) / 256;
    int st = tid*per, en = st + per; if (en > n) en = n;
    int s = 0;
    for (int i = st; i < en; i++) s += cnt[i];
    part[tid] = s;
    __syncthreads();
    for (int o = 1; o < 256; o <<= 1){
        int v = (tid >= o) ? part[tid - o] : 0;
        __syncthreads();
        part[tid] += v;
        __syncthreads();
    }
    int base = tid ? part[tid - 1] : 0;
    for (int i = st; i < en; i++){ off[i] = base; base += cnt[i]; }
    if (tid == 255) off[n] = part[255];
}

// ---------------- attention CSR build, both graphs (z-batched) -------------
__global__ void build_att2_k(const int* __restrict__ ge, const int* __restrict__ de,
                             int* __restrict__ cur0, int* __restrict__ cur1,
                             const int* __restrict__ off0, const int* __restrict__ off1,
                             int* __restrict__ payg, int* __restrict__ payd){
    int i = blockIdx.x*blockDim.x + threadIdx.x;
    if (i >= NE_) return;
    const int* src; const int* tgt; int* cur; const int* off; int* pay;
    if (blockIdx.z == 0){ src = ge; tgt = ge + NE_; cur = cur0; off = off0; pay = payg; }
    else                { src = de; tgt = de + NE_; cur = cur1; off = off1; pay = payd; }
    int t = tgt[i];
    int p = atomicAdd(&cur[t], 1);
    pay[off[t] + p] = src[i];
}

// ---------------- adjacency CSR build + dropout weights (z-batched) --------
__global__ void build_adj2_k(const int* __restrict__ arows, const int* __restrict__ acols,
                             const float* __restrict__ vals,
                             const unsigned* __restrict__ m1, const unsigned* __restrict__ m2,
                             int* __restrict__ cur2, int* __restrict__ cur3,
                             const int* __restrict__ off2, const int* __restrict__ off3,
                             int* __restrict__ pc1, int* __restrict__ pc2,
                             float* __restrict__ pw1, float* __restrict__ pw2){
    int i = blockIdx.x*blockDim.x + threadIdx.x;
    if (i >= NNZ_) return;
    const int* keys; const int* other; const unsigned* mask;
    int* cur; const int* off; int* pcol; float* pw;
    if (blockIdx.z == 0){ keys = arows; other = acols; mask = m1; cur = cur2; off = off2; pcol = pc1; pw = pw1; }
    else                { keys = acols; other = arows; mask = m2; cur = cur3; off = off3; pcol = pc2; pw = pw2; }
    int k = keys[i];
    int p = atomicAdd(&cur[k], 1);
    int slot = off[k] + p;
    pcol[slot] = other[i];
    pw[slot]   = mask[i] ? vals[i] * (1.0f/0.9f) : 0.f;
}

// ---------------- bf16 tensor-core GEMM with fused epilogues ---------------
// C[M,N] = A[M,K] @ B[K,N]; A bf16 row-major, Bt = B^T bf16 [N,K].
// M % 128 == 0, N % 128 == 0, K % 32 == 0 (padded; no guards).
// Optional: bf16 output (Cb), attention rowdot atomics (atta/al/ar, rows<rowlim),
// final-score atomics (W3/sv). blockIdx.z selects batch.
__global__ void hgemm_k(int M, int N, int K,
    const __nv_bfloat16* __restrict__ A0, const __nv_bfloat16* __restrict__ A1,
    const __nv_bfloat16* __restrict__ Bt,
    __nv_bfloat16* __restrict__ Cb0, __nv_bfloat16* __restrict__ Cb1,
    const float* __restrict__ bias, int relu,
    const float* __restrict__ atta,
    float* __restrict__ al0, float* __restrict__ ar0,
    float* __restrict__ al1, float* __restrict__ ar1, int rowlim,
    const float* __restrict__ W3, float* __restrict__ sv){
    const __nv_bfloat16* A = blockIdx.z ? A1 : A0;
    __nv_bfloat16* Cb = blockIdx.z ? Cb1 : Cb0;
    float* al = blockIdx.z ? al1 : al0;
    float* ar = blockIdx.z ? ar1 : ar0;
    __shared__ __nv_bfloat16 As[128][40];
    __shared__ __nv_bfloat16 Bs[128][40];
    int tid = threadIdx.x;
    int wid = tid >> 5, lane = tid & 31;
    int g = lane >> 2, tg = lane & 3;
    int wm = (wid & 1) * 64, wn = (wid >> 1) * 32;
    int row0 = blockIdx.y * 128, col0 = blockIdx.x * 128;
    float acc[4][4][4] = {};
    for (int k0 = 0; k0 < K; k0 += 32){
        #pragma unroll
        for (int i = 0; i < 2; i++){
            int idx = tid + i*256;
            int r = idx >> 2, c = (idx & 3) * 8;
            *(uint4*)&As[r][c] = *(const uint4*)(A  + (size_t)(row0 + r)*K + k0 + c);
            *(uint4*)&Bs[r][c] = *(const uint4*)(Bt + (size_t)(col0 + r)*K + k0 + c);
        }
        __syncthreads();
        #pragma unroll
        for (int ks = 0; ks < 2; ks++){
            unsigned af[4][4], bfrg[4][2];
            #pragma unroll
            for (int mt = 0; mt < 4; mt++){
                int rm = wm + mt*16;
                af[mt][0] = *(unsigned*)&As[rm + g    ][ks*16 + tg*2];
                af[mt][1] = *(unsigned*)&As[rm + g + 8][ks*16 + tg*2];
                af[mt][2] = *(unsigned*)&As[rm + g    ][ks*16 + tg*2 + 8];
                af[mt][3] = *(unsigned*)&As[rm + g + 8][ks*16 + tg*2 + 8];
            }
            #pragma unroll
            for (int nt = 0; nt < 4; nt++){
                int rn = wn + nt*8 + g;
                bfrg[nt][0] = *(unsigned*)&Bs[rn][ks*16 + tg*2];
                bfrg[nt][1] = *(unsigned*)&Bs[rn][ks*16 + tg*2 + 8];
            }
            #pragma unroll
            for (int mt = 0; mt < 4; mt++)
                #pragma unroll
                for (int nt = 0; nt < 4; nt++)
                    asm volatile(
                        "mma.sync.aligned.m16n8k16.row.col.f32.bf16.bf16.f32 "
                        "{%0,%1,%2,%3},{%4,%5,%6,%7},{%8,%9},{%0,%1,%2,%3};"
                        : "+f"(acc[mt][nt][0]), "+f"(acc[mt][nt][1]),
                          "+f"(acc[mt][nt][2]), "+f"(acc[mt][nt][3])
                        : "r"(af[mt][0]), "r"(af[mt][1]), "r"(af[mt][2]), "r"(af[mt][3]),
                          "r"(bfrg[nt][0]), "r"(bfrg[nt][1]));
        }
        __syncthreads();
    }
    float p1[4][2] = {}, p2[4][2] = {};
    #pragma unroll
    for (int mt = 0; mt < 4; mt++){
        #pragma unroll
        for (int nt = 0; nt < 4; nt++){
            int col = col0 + wn + nt*8 + tg*2;
            float b0v = 0.f, b1v = 0.f;
            if (bias){ b0v = bias[col]; b1v = bias[col+1]; }
            #pragma unroll
            for (int h = 0; h < 2; h++){
                int row = row0 + wm + mt*16 + g + h*8;
                float v0 = acc[mt][nt][h*2+0] + b0v;
                float v1 = acc[mt][nt][h*2+1] + b1v;
                if (relu){ v0 = fmaxf(v0, 0.f); v1 = fmaxf(v1, 0.f); }
                if (Cb)
                    *(__nv_bfloat162*)(Cb + (size_t)row*N + col) =
                        __floats2bfloat162_rn(v0, v1);
                if (atta){
                    float r0 = bfr(v0), r1 = bfr(v1);   // match stored bf16 h
                    p1[mt][h] += r0*atta[col]       + r1*atta[col+1];
                    p2[mt][h] += r0*atta[DIM+col]   + r1*atta[DIM+col+1];
                }
                if (W3) p1[mt][h] += v0*W3[col] + v1*W3[col+1];
            }
        }
    }
    if (atta || W3){
        #pragma unroll
        for (int mt = 0; mt < 4; mt++){
            #pragma unroll
            for (int h = 0; h < 2; h++){
                int row = row0 + wm + mt*16 + g + h*8;
                float a = p1[mt][h];
                a += __shfl_xor_sync(0xffffffffu, a, 1);
                a += __shfl_xor_sync(0xffffffffu, a, 2);
                if (atta){
                    float b = p2[mt][h];
                    b += __shfl_xor_sync(0xffffffffu, b, 1);
                    b += __shfl_xor_sync(0xffffffffu, b, 2);
                    if (tg == 0 && row < rowlim){
                        atomicAdd(&al[row], a);
                        atomicAdd(&ar[row], b);
                    }
                } else if (tg == 0){
                    atomicAdd(&sv[row], a);
                }
            }
        }
    }
}

// ---------------- fused CSR attention: softmax + aggregate + combine -------
// out[t] = bf16( 0.1 * (sum_e ex_e * h[src_e]) / (sum ex + 1e-9) + base[t] )
__global__ void att_csr_k(const int* __restrict__ off, const int* __restrict__ pay,
                          const float* __restrict__ al, const float* __restrict__ ar,
                          const __nv_bfloat16* __restrict__ h,
                          const float* __restrict__ base,
                          __nv_bfloat16* __restrict__ out, int n){
    int t = (blockIdx.x*blockDim.x + threadIdx.x) >> 5;
    int lane = threadIdx.x & 31;
    if (t >= n) return;
    int s0 = off[t], s1 = off[t+1];
    float art = ar[t];
    float m = -1e30f;
    for (int i = s0 + lane; i < s1; i += 32){
        float x = al[pay[i]] + art;
        x = x > 0.f ? x : 0.2f*x;
        m = fmaxf(m, x);
    }
    #pragma unroll
    for (int o = 16; o; o >>= 1) m = fmaxf(m, __shfl_xor_sync(0xffffffffu, m, o));
    float den = 0.f;
    float acc[8] = {};
    const uint4* hb = (const uint4*)h;
    for (int i = s0; i < s1; i++){
        int s = pay[i];
        float x = al[s] + art;
        x = x > 0.f ? x : 0.2f*x;
        float ex = __expf(x - m);
        den += ex;
        uint4 hv = hb[(size_t)s*32 + lane];
        float f[8]; unpack8(hv, f);
        #pragma unroll
        for (int j = 0; j < 8; j++) acc[j] += ex*f[j];
    }
    float dinv = 0.1f / (den + 1e-9f);
    const float4* bp = (const float4*)base + (size_t)t*64 + lane*2;
    float4 b0 = bp[0], b1 = bp[1];
    float o[8];
    o[0]=acc[0]*dinv+b0.x; o[1]=acc[1]*dinv+b0.y; o[2]=acc[2]*dinv+b0.z; o[3]=acc[3]*dinv+b0.w;
    o[4]=acc[4]*dinv+b1.x; o[5]=acc[5]*dinv+b1.y; o[6]=acc[6]*dinv+b1.z; o[7]=acc[7]*dinv+b1.w;
    ((uint4*)out)[(size_t)t*32 + lane] = pack8(o);
}

// ---------------- CSR SpMM directly into MLP input rows --------------------
// warp w < B_      : Eg row uids[w]  -> catb[w][0:256] and catb[w+B_][0:256]
// B_ <= w < 2B_    : Ed row pos[w-B_] -> catb[w-B_][256:512]
// 2B_ <= w < 3B_   : Ed row neg[w-2B_]-> catb[w-B_][256:512]  (i.e. row +B_)
__global__ void spmm_cat_k(const int* __restrict__ off2, const int* __restrict__ pc1,
                           const float* __restrict__ pw1,
                           const int* __restrict__ off3, const int* __restrict__ pc2,
                           const float* __restrict__ pw2,
                           const __nv_bfloat16* __restrict__ Eg0b,
                           const __nv_bfloat16* __restrict__ Ed0b,
                           const int* __restrict__ uids, const int* __restrict__ pos,
                           const int* __restrict__ neg,
                           __nv_bfloat16* __restrict__ catb){
    int w = (blockIdx.x*blockDim.x + threadIdx.x) >> 5;
    int lane = threadIdx.x & 31;
    if (w >= 3*B_) return;
    const int* off; const int* pc; const float* pw; const uint4* src;
    int r; uint4* dst0; uint4* dst1 = nullptr;
    uint4* cb = (uint4*)catb;
    if (w < B_){
        r = uids[w]; off = off2; pc = pc1; pw = pw1; src = (const uint4*)Ed0b;
        dst0 = cb + (size_t)w*64 + lane;
        dst1 = cb + (size_t)(w + B_)*64 + lane;
    } else if (w < 2*B_){
        int b = w - B_;
        r = pos[b]; off = off3; pc = pc2; pw = pw2; src = (const uint4*)Eg0b;
        dst0 = cb + (size_t)b*64 + 32 + lane;
    } else {
        int b = w - 2*B_;
        r = neg[b]; off = off3; pc = pc2; pw = pw2; src = (const uint4*)Eg0b;
        dst0 = cb + (size_t)(b + B_)*64 + 32 + lane;
    }
    int s0 = off[r], s1 = off[r+1];
    float acc[8] = {};
    for (int i = s0; i < s1; i++){
        float v = pw[i];
        if (v == 0.f) continue;
        int c = pc[i];
        uint4 sv = src[(size_t)c*32 + lane];
        float f[8]; unpack8(sv, f);
        #pragma unroll
        for (int j = 0; j < 8; j++) acc[j] += v*f[j];
    }
    uint4 o = pack8(acc);
    *dst0 = o;
    if (dst1) *dst1 = o;
}

// ---------------- loss_r reduction (adds b3 to scores) ---------------------
__global__ void loss_k(const float* __restrict__ s, const float* __restrict__ b3,
                       int B, double* acc){
    __shared__ double sh[256];
    float b3v = b3[0];
    double local = 0.0;
    for (int i = blockIdx.x*blockDim.x + threadIdx.x; i < B; i += gridDim.x*blockDim.x){
        double ps = s[i] + b3v, ns = s[B + i] + b3v;
        local += softplusd(-ps) + softplusd(ns) + softplusd(ns - ps);
    }
    sh[threadIdx.x] = local;
    __syncthreads();
    for (int st = 128; st; st >>= 1){
        if (threadIdx.x < st) sh[threadIdx.x] += sh[threadIdx.x + st];
        __syncthreads();
    }
    if (threadIdx.x == 0) atomicAdd(acc, sh[0]);
}

// ---------------- sum of squares over all 16 params, one launch ------------
__global__ void sumsq16_k(P16 a, double* acc){
    const float* p = a.p[blockIdx.y];
    int n = a.n[blockIdx.y];
    __shared__ double sh[256];
    double local = 0.0;
    for (int i = blockIdx.x*blockDim.x + threadIdx.x; i < n; i += gridDim.x*blockDim.x){
        double v = p[i];
        local += v*v;
    }
    sh[threadIdx.x] = local;
    __syncthreads();
    for (int st = 128; st; st >>= 1){
        if (threadIdx.x < st) sh[threadIdx.x] += sh[threadIdx.x + st];
        __syncthreads();
    }
    if (threadIdx.x == 0 && sh[0] != 0.0) atomicAdd(acc, sh[0]);
}

// ---------------- final combine --------------------------------------------
__global__ void final_k(const double* lr, const double* reg, float* out, int B){
    double l_r = (*lr) / (double)B;
    out[0] = (float)(1e-7 * (*reg) + l_r);
    out[1] = (float)l_r;
    out[2] = 0.f;
}

// ---------------- launch ----------------------------------------------------
extern "C" void kernel_launch(void* const* d_in, const int* in_sizes, int n_in,
                              void* d_out, int out_size){
    const float* Eg0  = (const float*)d_in[0];
    const float* Ed0  = (const float*)d_in[1];
    const float* attW = (const float*)d_in[2];
    const float* atta = (const float*)d_in[3];
    const float* W1   = (const float*)d_in[6];
    const float* b1   = (const float*)d_in[7];
    const float* W2   = (const float*)d_in[8];
    const float* b2   = (const float*)d_in[9];
    const float* W3   = (const float*)d_in[10];
    const float* b3   = (const float*)d_in[11];
    const float* adj_vals = (const float*)d_in[16];
    const int* uids = (const int*)d_in[17];
    const int* pos  = (const int*)d_in[19];
    const int* neg  = (const int*)d_in[20];
    const int* ge   = (const int*)d_in[21];
    const int* de   = (const int*)d_in[22];
    const int* arows = (const int*)d_in[23];
    const int* acols = (const int*)d_in[24];
    const unsigned* drop1 = (const unsigned*)d_in[25];
    const unsigned* drop2 = (const unsigned*)d_in[26];
    float* out = (float*)d_out;

    float *alg,*arg,*ald,*ard,*sv,*pw1,*pw2;
    int *ctl,*offs,*payg,*payd,*pc1,*pc2;
    __nv_bfloat16 *Eg0h,*Ed0h,*hgb,*hdb,*Eg0b,*Ed0b;
    __nv_bfloat16 *attWt,*W1t,*W2t,*catb,*h1b;
    double *lr,*reg;
    cudaGetSymbolAddress((void**)&alg,  d_alg);
    cudaGetSymbolAddress((void**)&arg,  d_arg_);
    cudaGetSymbolAddress((void**)&ald,  d_ald);
    cudaGetSymbolAddress((void**)&ard,  d_ard);
    cudaGetSymbolAddress((void**)&sv,   d_s);
    cudaGetSymbolAddress((void**)&ctl,  d_ctl);
    cudaGetSymbolAddress((void**)&offs, d_off);
    cudaGetSymbolAddress((void**)&payg, d_payg);
    cudaGetSymbolAddress((void**)&payd, d_payd);
    cudaGetSymbolAddress((void**)&pc1,  d_pc1);
    cudaGetSymbolAddress((void**)&pc2,  d_pc2);
    cudaGetSymbolAddress((void**)&pw1,  d_pw1);
    cudaGetSymbolAddress((void**)&pw2,  d_pw2);
    cudaGetSymbolAddress((void**)&Eg0h, d_Eg0h);
    cudaGetSymbolAddress((void**)&Ed0h, d_Ed0h);
    cudaGetSymbolAddress((void**)&hgb,  d_hgb);
    cudaGetSymbolAddress((void**)&hdb,  d_hdb);
    cudaGetSymbolAddress((void**)&Eg0b, d_Eg0b);
    cudaGetSymbolAddress((void**)&Ed0b, d_Ed0b);
    cudaGetSymbolAddress((void**)&attWt,d_attWt);
    cudaGetSymbolAddress((void**)&W1t,  d_W1t);
    cudaGetSymbolAddress((void**)&W2t,  d_W2t);
    cudaGetSymbolAddress((void**)&catb, d_catb);
    cudaGetSymbolAddress((void**)&h1b,  d_h1b);
    cudaGetSymbolAddress((void**)&lr,   d_lr_acc);
    cudaGetSymbolAddress((void**)&reg,  d_reg_acc);

    const int NP1 = NN + 1;
    int* cnt0 = ctl;            int* cnt1 = ctl + NP1;
    int* cnt2 = ctl + 2*NP1;    int* cnt3 = ctl + 3*NP1;
    int* cur0 = ctl + 4*NP1;    int* cur1 = ctl + 5*NP1;
    int* cur2 = ctl + 6*NP1;    int* cur3 = ctl + 7*NP1;
    int* off0 = offs;           int* off1 = offs + NP1;
    int* off2 = offs + 2*NP1;   int* off3 = offs + 3*NP1;

    // fork-join streams (host-side objects only; cost is capture-time only)
    cudaStream_t sB, sC, sD;
    cudaStreamCreateWithFlags(&sB, cudaStreamNonBlocking);
    cudaStreamCreateWithFlags(&sC, cudaStreamNonBlocking);
    cudaStreamCreateWithFlags(&sD, cudaStreamNonBlocking);
    cudaEvent_t evRoot, evB, evW, evC, evF, evH;
    cudaEventCreateWithFlags(&evRoot, cudaEventDisableTiming);
    cudaEventCreateWithFlags(&evB,    cudaEventDisableTiming);
    cudaEventCreateWithFlags(&evW,    cudaEventDisableTiming);
    cudaEventCreateWithFlags(&evC,    cudaEventDisableTiming);
    cudaEventCreateWithFlags(&evF,    cudaEventDisableTiming);
    cudaEventCreateWithFlags(&evH,    cudaEventDisableTiming);

    cudaEventRecord(evRoot, 0);
    cudaStreamWaitEvent(sB, evRoot, 0);
    cudaStreamWaitEvent(sC, evRoot, 0);

    // ---- stream B: CSR build chain (5 launches) ----
    cudaMemsetAsync(ctl, 0, sizeof(int)*8*NP1, sB);
    hist4_k<<<(2*NE_+2*NNZ_+255)/256, 256, 0, sB>>>(ge+NE_, de+NE_, arows, acols,
                                                    cnt0, cnt1, cnt2, cnt3);
    ScanArgs sa;
    sa.cnt[0]=cnt0; sa.cnt[1]=cnt1; sa.cnt[2]=cnt2; sa.cnt[3]=cnt3;
    sa.off[0]=off0; sa.off[1]=off1; sa.off[2]=off2; sa.off[3]=off3;
    scan4_k<<<4, 256, 0, sB>>>(sa, NN);
    build_att2_k<<<dim3((NE_+255)/256, 1, 2), 256, 0, sB>>>(ge, de, cur0, cur1,
                                                            off0, off1, payg, payd);
    build_adj2_k<<<dim3((NNZ_+255)/256, 1, 2), 256, 0, sB>>>(arows, acols, adj_vals,
        drop1, drop2, cur2, cur3, off2, off3, pc1, pc2, pw1, pw2);
    cudaEventRecord(evB, sB);

    // ---- stream C: zeroing + weight transposes (evW), then regularizer (evC)
    cudaMemsetAsync(lr,  0, sizeof(double), sC);
    cudaMemsetAsync(reg, 0, sizeof(double), sC);
    cudaMemsetAsync(sv,  0, sizeof(float)*2*B_, sC);
    cudaMemsetAsync(alg, 0, sizeof(float)*NN, sC);
    cudaMemsetAsync(arg, 0, sizeof(float)*NN, sC);
    cudaMemsetAsync(ald, 0, sizeof(float)*NN, sC);
    cudaMemsetAsync(ard, 0, sizeof(float)*NN, sC);
    convT3_k<<<dim3((2*DIM*DIM+255)/256, 1, 3), 256, 0, sC>>>(attW, W1, W2,
                                                              attWt, W1t, W2t);
    cudaEventRecord(evW, sC);
    P16 pp;
    for (int i = 0; i < 16; i++){ pp.p[i] = (const float*)d_in[i]; pp.n[i] = in_sizes[i]; }
    sumsq16_k<<<dim3(48, 16), 256, 0, sC>>>(pp, reg);
    cudaEventRecord(evC, sC);

    // ---- main stream: conv -> GEMM(+rowdot) -> att -> spmm_cat -> MLP ----
    conv2_k<<<(2*NN*DIM/4+255)/256, 256>>>(Eg0, Ed0, Eg0h, Ed0h, NN*DIM/4);
    cudaStreamWaitEvent(0, evW, 0);
    hgemm_k<<<dim3(DIM/128, NNP/128, 2), 256>>>(NNP, DIM, DIM,
        Eg0h, Ed0h, attWt, hgb, hdb, nullptr, 0,
        atta, alg, arg, ald, ard, NN, nullptr, nullptr);

    // join CSR, fork gene/drug attention
    cudaStreamWaitEvent(0, evB, 0);
    cudaEventRecord(evF, 0);
    cudaStreamWaitEvent(sD, evF, 0);
    att_csr_k<<<(NN*32+255)/256, 256>>>(off0, payg, alg, arg, hgb, Eg0, Eg0b, NN);
    att_csr_k<<<(NN*32+255)/256, 256, 0, sD>>>(off1, payd, ald, ard, hdb, Ed0, Ed0b, NN);
    cudaEventRecord(evH, sD);
    cudaStreamWaitEvent(0, evH, 0);

    // SpMM straight into MLP input rows (uids/pos/neg only)
    spmm_cat_k<<<(3*B_*32+255)/256, 256>>>(off2, pc1, pw1, off3, pc2, pw2,
                                           Eg0b, Ed0b, uids, pos, neg, catb);

    // MLP: layer1 -> bf16 h1; layer2 fused with score atomics (no h2 buffer)
    hgemm_k<<<dim3(DIM/128, (2*B_)/128, 1), 256>>>(2*B_, DIM, 2*DIM,
        catb, catb, W1t, h1b, h1b, b1, 1,
        nullptr, nullptr, nullptr, nullptr, nullptr, 0, nullptr, nullptr);
    hgemm_k<<<dim3(DIM/128, (2*B_)/128, 1), 256>>>(2*B_, DIM, DIM,
        h1b, h1b, W2t, nullptr, nullptr, b2, 1,
        nullptr, nullptr, nullptr, nullptr, nullptr, 0, W3, sv);

    loss_k<<<64, 256>>>(sv, b3, B_, lr);
    cudaStreamWaitEvent(0, evC, 0);
    final_k<<<1, 1>>>(lr, reg, out, B_);

    cudaEventDestroy(evRoot); cudaEventDestroy(evB); cudaEventDestroy(evW);
    cudaEventDestroy(evC); cudaEventDestroy(evF); cudaEventDestroy(evH);
    cudaStreamDestroy(sB); cudaStreamDestroy(sC); cudaStreamDestroy(sD);
}